// round 1
// baseline (speedup 1.0000x reference)
#include <cuda_runtime.h>
#include <math.h>

#define NN   50000
#define EE   800000
#define ESL  (EE + NN)
#define INCH 128
#define HID  64
#define NH   4
#define HH   256
#define OUTN 16
#define OUTE 4

// ---------------- scratch (allocation-free rule: __device__ globals) ----------------
__device__ float    g_xp[(size_t)NN * HH];          // projected features (per layer, reused)
__device__ float    g_h1[(size_t)NN * HH];          // layer-1 output
__device__ float    g_agg[(size_t)NN * HH];         // aggregation accumulator
__device__ float    g_als[NN * NH];
__device__ float    g_ald[NN * NH];
__device__ unsigned g_menc[NN * NH];                // ordered-uint encoded segment max
__device__ float    g_den[NN * NH];
__device__ float    g_ealpha[(size_t)ESL * NH];     // per-edge alpha, then exp
__device__ float    g_WbT[OUTE * HH * HH];          // Wb transposed: [o*HH+j][i]
__device__ float    g_t[(size_t)NN * OUTE * HH];    // t[n, o*HH + j] = sum_i h[n,i] Wb[o,i,j]

// ---------------- helpers ----------------
__device__ __forceinline__ unsigned fenc(float f) {
    unsigned u = __float_as_uint(f);
    return (u & 0x80000000u) ? ~u : (u | 0x80000000u);
}
__device__ __forceinline__ float fdec(unsigned u) {
    return (u & 0x80000000u) ? __uint_as_float(u & 0x7fffffffu) : __uint_as_float(~u);
}

// ---------------- generic SGEMM (NT): C[M,Nc] = A[M,K] * B[Nc,K]^T (+bias) ----------------
// 64x64 tile, 256 threads, 4x4 micro-tile.
__global__ void sgemm_nt(const float* __restrict__ A, const float* __restrict__ B,
                         float* __restrict__ C, const float* __restrict__ bias,
                         int M, int Nc, int K) {
    __shared__ float As[16][68];
    __shared__ float Bs[16][68];
    int tx = threadIdx.x & 15;
    int ty = threadIdx.x >> 4;
    int bm = blockIdx.y * 64;
    int bn = blockIdx.x * 64;

    float acc[4][4] = {};
    for (int k0 = 0; k0 < K; k0 += 16) {
        for (int i = threadIdx.x; i < 64 * 16; i += 256) {
            int r = i >> 4, c = i & 15;
            int gr = bm + r;
            As[c][r] = (gr < M) ? A[(size_t)gr * K + k0 + c] : 0.f;
        }
        for (int i = threadIdx.x; i < 64 * 16; i += 256) {
            int r = i >> 4, c = i & 15;
            int gn = bn + r;
            Bs[c][r] = (gn < Nc) ? B[(size_t)gn * K + k0 + c] : 0.f;
        }
        __syncthreads();
#pragma unroll
        for (int kk = 0; kk < 16; kk++) {
            float4 a4 = *(const float4*)&As[kk][ty * 4];
            float4 b4 = *(const float4*)&Bs[kk][tx * 4];
            float a[4] = {a4.x, a4.y, a4.z, a4.w};
            float b[4] = {b4.x, b4.y, b4.z, b4.w};
#pragma unroll
            for (int i = 0; i < 4; i++)
#pragma unroll
                for (int j = 0; j < 4; j++) acc[i][j] = fmaf(a[i], b[j], acc[i][j]);
        }
        __syncthreads();
    }
#pragma unroll
    for (int i = 0; i < 4; i++) {
        int gm = bm + ty * 4 + i;
        if (gm >= M) continue;
#pragma unroll
        for (int j = 0; j < 4; j++) {
            int gn = bn + tx * 4 + j;
            if (gn < Nc) {
                float v = acc[i][j];
                if (bias) v += bias[gn];
                C[(size_t)gm * Nc + gn] = v;
            }
        }
    }
}

// ---------------- per-node attention logits ----------------
__global__ void k_al(const float* __restrict__ a_s, const float* __restrict__ a_d) {
    int idx = blockIdx.x * blockDim.x + threadIdx.x;
    if (idx >= NN * NH) return;
    int n = idx >> 2, h = idx & 3;
    const float* row = g_xp + (size_t)n * HH + h * HID;
    float s = 0.f, d = 0.f;
#pragma unroll
    for (int k = 0; k < HID; k++) {
        float v = row[k];
        s = fmaf(v, a_s[h * HID + k], s);
        d = fmaf(v, a_d[h * HID + k], d);
    }
    g_als[idx] = s;
    g_ald[idx] = d;
}

// ---------------- per-layer init: zero agg, reset max/den ----------------
__global__ void k_init() {
    int idx = blockIdx.x * blockDim.x + threadIdx.x;
    if (idx < NN * HH) g_agg[idx] = 0.f;
    if (idx < NN * NH) {
        g_menc[idx] = 0x007fffffu;  // fenc(-inf)
        g_den[idx] = 0.f;
    }
}

// ---------------- edge pass 1: alpha + segment max ----------------
__global__ void k_edge_max(const int* __restrict__ ei) {
    int idx = blockIdx.x * blockDim.x + threadIdx.x;
    if (idx >= ESL * NH) return;
    int e = idx >> 2, h = idx & 3;
    int s = (e < EE) ? ei[e] : (e - EE);
    int d = (e < EE) ? ei[EE + e] : (e - EE);
    float a = g_als[s * NH + h] + g_ald[d * NH + h];
    a = (a > 0.f) ? a : 0.2f * a;
    g_ealpha[idx] = a;
    atomicMax(&g_menc[d * NH + h], fenc(a));
}

// ---------------- edge pass 2: exp + denominator ----------------
__global__ void k_edge_exp(const int* __restrict__ ei) {
    int idx = blockIdx.x * blockDim.x + threadIdx.x;
    if (idx >= ESL * NH) return;
    int e = idx >> 2, h = idx & 3;
    int d = (e < EE) ? ei[EE + e] : (e - EE);
    float a = g_ealpha[idx];
    float m = fdec(g_menc[d * NH + h]);
    float ex = expf(a - m);
    g_ealpha[idx] = ex;
    atomicAdd(&g_den[d * NH + h], ex);
}

// ---------------- edge pass 3: weighted scatter-sum (warp per edge) ----------------
__global__ void k_agg(const int* __restrict__ ei) {
    int gw = (blockIdx.x * blockDim.x + threadIdx.x) >> 5;
    int lane = threadIdx.x & 31;
    if (gw >= ESL) return;
    int s = (gw < EE) ? ei[gw] : (gw - EE);
    int d = (gw < EE) ? ei[EE + gw] : (gw - EE);
    float coef[NH];
#pragma unroll
    for (int h = 0; h < NH; h++)
        coef[h] = g_ealpha[(size_t)gw * NH + h] / (g_den[d * NH + h] + 1e-16f);
    const float4* xr = (const float4*)(g_xp + (size_t)s * HH);
    float* ar = g_agg + (size_t)d * HH;
#pragma unroll
    for (int it = 0; it < 2; it++) {
        int c4 = lane + it * 32;          // float4 index, 0..63
        float4 v = xr[c4];
        float cf = coef[c4 >> 4];         // (c4*4)/64
        atomicAdd(&ar[c4 * 4 + 0], v.x * cf);
        atomicAdd(&ar[c4 * 4 + 1], v.y * cf);
        atomicAdd(&ar[c4 * 4 + 2], v.z * cf);
        atomicAdd(&ar[c4 * 4 + 3], v.w * cf);
    }
}

// ---------------- bias + ELU ----------------
__global__ void k_bias_elu(const float* __restrict__ b, float* __restrict__ out) {
    int idx = blockIdx.x * blockDim.x + threadIdx.x;
    if (idx >= NN * HH) return;
    float v = g_agg[idx] + b[idx & (HH - 1)];
    out[idx] = (v > 0.f) ? v : expm1f(v);
}

// ---------------- transpose Wb[o,i,j] -> WbT[(o*HH+j), i] ----------------
__global__ void k_wbt(const float* __restrict__ Wb) {
    int idx = blockIdx.x * blockDim.x + threadIdx.x;
    if (idx >= OUTE * HH * HH) return;
    int o = idx / (HH * HH);
    int i = (idx / HH) % HH;
    int j = idx % HH;
    g_WbT[((size_t)o * HH + j) * HH + i] = Wb[idx];
}

// ---------------- edge bilinear: warp per edge ----------------
__global__ void k_edge_bilinear(const int* __restrict__ ei, const float* __restrict__ h2,
                                const float* __restrict__ bb, float* __restrict__ out_edge) {
    int gw = (blockIdx.x * blockDim.x + threadIdx.x) >> 5;
    int lane = threadIdx.x & 31;
    if (gw >= EE) return;
    int s = ei[gw];
    int d = ei[EE + gw];
    const float4* hd4 = (const float4*)(h2 + (size_t)d * HH);
    float4 hv0 = hd4[lane];
    float4 hv1 = hd4[lane + 32];
    const float4* tp = (const float4*)(g_t + (size_t)s * (OUTE * HH));
#pragma unroll
    for (int o = 0; o < OUTE; o++) {
        float4 t0 = tp[o * 64 + lane];
        float4 t1 = tp[o * 64 + lane + 32];
        float acc = t0.x * hv0.x + t0.y * hv0.y + t0.z * hv0.z + t0.w * hv0.w
                  + t1.x * hv1.x + t1.y * hv1.y + t1.z * hv1.z + t1.w * hv1.w;
#pragma unroll
        for (int off = 16; off > 0; off >>= 1)
            acc += __shfl_xor_sync(0xffffffffu, acc, off);
        if (lane == 0) out_edge[(size_t)gw * OUTE + o] = acc + bb[o];
    }
}

// ---------------- host ----------------
extern "C" void kernel_launch(void* const* d_in, const int* in_sizes, int n_in,
                              void* d_out, int out_size) {
    const float* x   = (const float*)d_in[0];
    const int*   ei  = (const int*)d_in[1];
    const float* W1  = (const float*)d_in[2];
    const float* as1 = (const float*)d_in[3];
    const float* ad1 = (const float*)d_in[4];
    const float* b1  = (const float*)d_in[5];
    const float* W2  = (const float*)d_in[6];
    const float* as2 = (const float*)d_in[7];
    const float* ad2 = (const float*)d_in[8];
    const float* b2  = (const float*)d_in[9];
    const float* Wn  = (const float*)d_in[10];
    const float* bn  = (const float*)d_in[11];
    const float* Wb  = (const float*)d_in[12];
    const float* bb  = (const float*)d_in[13];

    float* out_node = (float*)d_out;
    float* out_edge = out_node + (size_t)NN * OUTN;
    float* out_h    = out_edge + (size_t)EE * OUTE;

    float *p_xp, *p_h1, *p_t, *p_WbT;
    cudaGetSymbolAddress((void**)&p_xp, g_xp);
    cudaGetSymbolAddress((void**)&p_h1, g_h1);
    cudaGetSymbolAddress((void**)&p_t, g_t);
    cudaGetSymbolAddress((void**)&p_WbT, g_WbT);

    dim3 blk(256);
    int g_elem  = (NN * HH + 255) / 256;   // 12.8M elems
    int g_edge4 = (ESL * NH + 255) / 256;  // 3.4M threads
    int g_aggw  = (ESL + 7) / 8;           // warp per edge
    int g_al    = (NN * NH + 255) / 256;

    // ---- layer 1 ----
    {
        dim3 grid((HH + 63) / 64, (NN + 63) / 64);
        sgemm_nt<<<grid, blk>>>(x, W1, p_xp, nullptr, NN, HH, INCH);
    }
    k_al<<<g_al, blk>>>(as1, ad1);
    k_init<<<g_elem, blk>>>();
    k_edge_max<<<g_edge4, blk>>>(ei);
    k_edge_exp<<<g_edge4, blk>>>(ei);
    k_agg<<<g_aggw, blk>>>(ei);
    k_bias_elu<<<g_elem, blk>>>(b1, p_h1);

    // ---- layer 2 ----
    {
        dim3 grid((HH + 63) / 64, (NN + 63) / 64);
        sgemm_nt<<<grid, blk>>>(p_h1, W2, p_xp, nullptr, NN, HH, HH);
    }
    k_al<<<g_al, blk>>>(as2, ad2);
    k_init<<<g_elem, blk>>>();
    k_edge_max<<<g_edge4, blk>>>(ei);
    k_edge_exp<<<g_edge4, blk>>>(ei);
    k_agg<<<g_aggw, blk>>>(ei);
    k_bias_elu<<<g_elem, blk>>>(b2, out_h);   // final h -> output

    // ---- node predictor ----
    {
        dim3 grid((OUTN + 63) / 64, (NN + 63) / 64);
        sgemm_nt<<<grid, blk>>>(out_h, Wn, out_node, bn, NN, OUTN, HH);
    }

    // ---- edge bilinear: t = h @ Wb (per-node), then per-edge dot ----
    k_wbt<<<(OUTE * HH * HH + 255) / 256, blk>>>(Wb);
    {
        dim3 grid((OUTE * HH + 63) / 64, (NN + 63) / 64);
        sgemm_nt<<<grid, blk>>>(out_h, p_WbT, p_t, nullptr, NN, OUTE * HH, HH);
    }
    k_edge_bilinear<<<(EE + 7) / 8, blk>>>(ei, out_h, bb, out_edge);
}

// round 3
// speedup vs baseline: 1.8898x; 1.8898x over previous
#include <cuda_runtime.h>
#include <cuda_bf16.h>
#include <math.h>

#define NN   50000
#define EE   800000
#define ESL  (EE + NN)
#define INCH 128
#define HID  64
#define NH   4
#define HH   256
#define OUTN 16
#define OUTE 4

// ---------------- scratch (__device__ globals: allocation-free rule) ----------------
__device__ float         g_xp[(size_t)NN * HH];
__device__ float         g_h1[(size_t)NN * HH];
__device__ float         g_agg[(size_t)NN * HH];
__device__ float         g_als[NN * NH];
__device__ float         g_ald[NN * NH];
__device__ unsigned      g_menc[NN * NH];
__device__ float         g_den[NN * NH];
__device__ float         g_ealpha[(size_t)ESL * NH];
__device__ float         g_t[(size_t)NN * OUTE * HH];          // [N, 1024]
__device__ __nv_bfloat16 g_a3[(size_t)NN * (3 * HH)];          // 3-way split activations
__device__ __nv_bfloat16 g_b3[(size_t)(OUTE * HH) * (3 * HH)]; // 3-way split weights

// ---------------- helpers ----------------
__device__ __forceinline__ unsigned fenc(float f) {
    unsigned u = __float_as_uint(f);
    return (u & 0x80000000u) ? ~u : (u | 0x80000000u);
}
__device__ __forceinline__ float fdec(unsigned u) {
    return (u & 0x80000000u) ? __uint_as_float(u & 0x7fffffffu) : __uint_as_float(~u);
}
__device__ __forceinline__ void ldsm_x4(unsigned &r0, unsigned &r1, unsigned &r2, unsigned &r3, unsigned addr) {
    asm volatile("ldmatrix.sync.aligned.m8n8.x4.shared.b16 {%0,%1,%2,%3}, [%4];"
                 : "=r"(r0), "=r"(r1), "=r"(r2), "=r"(r3) : "r"(addr));
}
__device__ __forceinline__ void mma_bf16(float &c0, float &c1, float &c2, float &c3,
                                         unsigned a0, unsigned a1, unsigned a2, unsigned a3,
                                         unsigned b0, unsigned b1) {
    asm volatile("mma.sync.aligned.m16n8k16.row.col.f32.bf16.bf16.f32 "
                 "{%0,%1,%2,%3}, {%4,%5,%6,%7}, {%8,%9}, {%0,%1,%2,%3};"
                 : "+f"(c0), "+f"(c1), "+f"(c2), "+f"(c3)
                 : "r"(a0), "r"(a1), "r"(a2), "r"(a3), "r"(b0), "r"(b1));
}
__device__ __forceinline__ void cp16(unsigned dst, const void* src) {
    asm volatile("cp.async.cg.shared.global [%0], [%1], 16;" :: "r"(dst), "l"(src));
}
__device__ __forceinline__ void red4(float* p, float a, float b, float c, float d) {
    asm volatile("red.global.add.v4.f32 [%0], {%1,%2,%3,%4};"
                 :: "l"(p), "f"(a), "f"(b), "f"(c), "f"(d) : "memory");
}

// ---------------- 3-way split fp32 -> bf16, out layout [R, 3K] = [hi | lo | hi] ----------------
__global__ void k_split3(const float* __restrict__ in, __nv_bfloat16* __restrict__ out, int R, int K) {
    int idx = blockIdx.x * blockDim.x + threadIdx.x;
    if (idx >= R * K) return;
    int r = idx / K, k = idx - r * K;
    float v = in[idx];
    __nv_bfloat16 hi = __float2bfloat16(v);
    float lo = v - __bfloat162float(hi);
    size_t base = (size_t)r * (3 * K);
    out[base + k] = hi;
    out[base + K + k] = __float2bfloat16(lo);
    out[base + 2 * K + k] = hi;
}

// Wb[o,i,j] -> split-transposed B3 row (o*HH+j): [hi(i) | hi(i) | lo(i)]
__global__ void k_wbt_split3(const float* __restrict__ Wb) {
    int idx = blockIdx.x * blockDim.x + threadIdx.x;
    if (idx >= OUTE * HH * HH) return;
    int o = idx / (HH * HH);
    int i = (idx / HH) % HH;
    int j = idx % HH;
    float v = Wb[idx];
    __nv_bfloat16 hi = __float2bfloat16(v);
    float lo = v - __bfloat162float(hi);
    size_t base = ((size_t)o * HH + j) * (3 * HH);
    g_b3[base + i] = hi;
    g_b3[base + HH + i] = hi;
    g_b3[base + 2 * HH + i] = __float2bfloat16(lo);
}

// fp32 weights W[R,K] -> split B3 rows [b_hi | b_hi | b_lo]
__global__ void k_wsplit3(const float* __restrict__ W, __nv_bfloat16* __restrict__ out, int R, int K) {
    int idx = blockIdx.x * blockDim.x + threadIdx.x;
    if (idx >= R * K) return;
    int r = idx / K, k = idx - r * K;
    float v = W[idx];
    __nv_bfloat16 hi = __float2bfloat16(v);
    float lo = v - __bfloat162float(hi);
    size_t base = (size_t)r * (3 * K);
    out[base + k] = hi;
    out[base + K + k] = hi;
    out[base + 2 * K + k] = __float2bfloat16(lo);
}

// ---------------- bf16 tensor-core GEMM: C[M,Nc] = A[M,K2] * B[Nc,K2]^T ----------------
// 128x64 block tile, BK=32, 8 warps (4x2) of 32x32, double-buffered cp.async.
__global__ void __launch_bounds__(256) gemm_bf16_nt(const __nv_bfloat16* __restrict__ A,
                                                    const __nv_bfloat16* __restrict__ B,
                                                    float* __restrict__ C,
                                                    int M, int Nc, int K2) {
    __shared__ __nv_bfloat16 As[2][128 * 32];
    __shared__ __nv_bfloat16 Bs[2][64 * 32];
    const int tid = threadIdx.x;
    const int wid = tid >> 5, lane = tid & 31;
    const int bm = blockIdx.y * 128, bn = blockIdx.x * 64;
    const int wm = (wid >> 1) * 32, wn = (wid & 1) * 32;

    const unsigned as_base = (unsigned)__cvta_generic_to_shared(&As[0][0]);
    const unsigned bs_base = (unsigned)__cvta_generic_to_shared(&Bs[0][0]);

    float acc[2][4][4];
#pragma unroll
    for (int i = 0; i < 2; i++)
#pragma unroll
        for (int j = 0; j < 4; j++)
#pragma unroll
            for (int k = 0; k < 4; k++) acc[i][j][k] = 0.f;

    const int KT = K2 >> 5;

    const int aq0_row = tid >> 2,         aq0_c = tid & 3;
    const int aq1_row = (tid + 256) >> 2, aq1_c = tid & 3;
    const int bq_row = tid >> 2,          bq_c = tid & 3;

#define SWZ(row, c) (((row) * 4 + ((c) ^ (((row) >> 1) & 3))) * 16)

    auto load_stage = [&](int kt, int s) {
        const int k0 = kt * 32;
        const unsigned as_s = as_base + s * 8192;
        const unsigned bs_s = bs_base + s * 4096;
        {
            int gr = bm + aq0_row;
            unsigned dst = as_s + SWZ(aq0_row, aq0_c);
            if (gr < M) cp16(dst, A + (size_t)gr * K2 + k0 + aq0_c * 8);
            else { uint4 z = {0,0,0,0}; *(uint4*)&As[s][(size_t)(SWZ(aq0_row, aq0_c) >> 1)] = z; }
        }
        {
            int gr = bm + aq1_row;
            unsigned dst = as_s + SWZ(aq1_row, aq1_c);
            if (gr < M) cp16(dst, A + (size_t)gr * K2 + k0 + aq1_c * 8);
            else { uint4 z = {0,0,0,0}; *(uint4*)&As[s][(size_t)(SWZ(aq1_row, aq1_c) >> 1)] = z; }
        }
        {
            int gn = bn + bq_row;
            unsigned dst = bs_s + SWZ(bq_row, bq_c);
            if (gn < Nc) cp16(dst, B + (size_t)gn * K2 + k0 + bq_c * 8);
            else { uint4 z = {0,0,0,0}; *(uint4*)&Bs[s][(size_t)(SWZ(bq_row, bq_c) >> 1)] = z; }
        }
        asm volatile("cp.async.commit_group;");
    };

    load_stage(0, 0);
    for (int kt = 0; kt < KT; kt++) {
        const int s = kt & 1;
        asm volatile("cp.async.wait_group 0;");
        __syncthreads();
        if (kt + 1 < KT) load_stage(kt + 1, (kt + 1) & 1);

        const unsigned as_s = as_base + s * 8192;
        const unsigned bs_s = bs_base + s * 4096;
#pragma unroll
        for (int ks = 0; ks < 2; ks++) {
            unsigned a[2][4], b[2][4];
            const int kc = ks * 2 + (lane >> 4);
#pragma unroll
            for (int mf = 0; mf < 2; mf++) {
                int row = wm + mf * 16 + (lane & 15);
                ldsm_x4(a[mf][0], a[mf][1], a[mf][2], a[mf][3], as_s + SWZ(row, kc));
            }
#pragma unroll
            for (int nf2 = 0; nf2 < 2; nf2++) {
                int row = wn + nf2 * 16 + (lane & 15);
                ldsm_x4(b[nf2][0], b[nf2][1], b[nf2][2], b[nf2][3], bs_s + SWZ(row, kc));
            }
#pragma unroll
            for (int mf = 0; mf < 2; mf++)
#pragma unroll
                for (int nf = 0; nf < 4; nf++) {
                    int nf2 = nf >> 1, w = nf & 1;
                    mma_bf16(acc[mf][nf][0], acc[mf][nf][1], acc[mf][nf][2], acc[mf][nf][3],
                             a[mf][0], a[mf][1], a[mf][2], a[mf][3],
                             b[nf2][w], b[nf2][w + 2]);
                }
        }
        __syncthreads();
    }
#undef SWZ

#pragma unroll
    for (int mf = 0; mf < 2; mf++)
#pragma unroll
        for (int nf = 0; nf < 4; nf++) {
            int r0 = bm + wm + mf * 16 + (lane >> 2);
            int c0 = bn + wn + nf * 8 + (lane & 3) * 2;
            if (c0 < Nc) {
                if (r0 < M) {
                    float2 v = {acc[mf][nf][0], acc[mf][nf][1]};
                    *(float2*)&C[(size_t)r0 * Nc + c0] = v;
                }
                if (r0 + 8 < M) {
                    float2 v = {acc[mf][nf][2], acc[mf][nf][3]};
                    *(float2*)&C[(size_t)(r0 + 8) * Nc + c0] = v;
                }
            }
        }
}

// ---------------- fp32 SGEMM (small node predictor) ----------------
__global__ void sgemm_nt(const float* __restrict__ A, const float* __restrict__ B,
                         float* __restrict__ C, const float* __restrict__ bias,
                         int M, int Nc, int K) {
    __shared__ float As[16][68];
    __shared__ float Bs[16][68];
    int tx = threadIdx.x & 15;
    int ty = threadIdx.x >> 4;
    int bm = blockIdx.y * 64;
    int bn = blockIdx.x * 64;

    float acc[4][4] = {};
    for (int k0 = 0; k0 < K; k0 += 16) {
        for (int i = threadIdx.x; i < 64 * 16; i += 256) {
            int r = i >> 4, c = i & 15;
            int gr = bm + r;
            As[c][r] = (gr < M) ? A[(size_t)gr * K + k0 + c] : 0.f;
        }
        for (int i = threadIdx.x; i < 64 * 16; i += 256) {
            int r = i >> 4, c = i & 15;
            int gn = bn + r;
            Bs[c][r] = (gn < Nc) ? B[(size_t)gn * K + k0 + c] : 0.f;
        }
        __syncthreads();
#pragma unroll
        for (int kk = 0; kk < 16; kk++) {
            float4 a4 = *(const float4*)&As[kk][ty * 4];
            float4 b4 = *(const float4*)&Bs[kk][tx * 4];
            float a[4] = {a4.x, a4.y, a4.z, a4.w};
            float b[4] = {b4.x, b4.y, b4.z, b4.w};
#pragma unroll
            for (int i = 0; i < 4; i++)
#pragma unroll
                for (int j = 0; j < 4; j++) acc[i][j] = fmaf(a[i], b[j], acc[i][j]);
        }
        __syncthreads();
    }
#pragma unroll
    for (int i = 0; i < 4; i++) {
        int gm = bm + ty * 4 + i;
        if (gm >= M) continue;
#pragma unroll
        for (int j = 0; j < 4; j++) {
            int gn = bn + tx * 4 + j;
            if (gn < Nc) {
                float v = acc[i][j];
                if (bias) v += bias[gn];
                C[(size_t)gm * Nc + gn] = v;
            }
        }
    }
}

// ---------------- per-node attention logits ----------------
__global__ void k_al(const float* __restrict__ a_s, const float* __restrict__ a_d) {
    int idx = blockIdx.x * blockDim.x + threadIdx.x;
    if (idx >= NN * NH) return;
    int n = idx >> 2, h = idx & 3;
    const float* row = g_xp + (size_t)n * HH + h * HID;
    float s = 0.f, d = 0.f;
#pragma unroll
    for (int k = 0; k < HID; k++) {
        float v = row[k];
        s = fmaf(v, a_s[h * HID + k], s);
        d = fmaf(v, a_d[h * HID + k], d);
    }
    g_als[idx] = s;
    g_ald[idx] = d;
}

// ---------------- reset max/den ----------------
__global__ void k_init_md() {
    int idx = blockIdx.x * blockDim.x + threadIdx.x;
    if (idx < NN * NH) {
        g_menc[idx] = 0x007fffffu;  // fenc(-inf)
        g_den[idx] = 0.f;
    }
}

// ---------------- edge pass 1: alpha + segment max ----------------
__global__ void k_edge_max(const int* __restrict__ ei) {
    int idx = blockIdx.x * blockDim.x + threadIdx.x;
    if (idx >= ESL * NH) return;
    int e = idx >> 2, h = idx & 3;
    int s = (e < EE) ? ei[e] : (e - EE);
    int d = (e < EE) ? ei[EE + e] : (e - EE);
    float a = g_als[s * NH + h] + g_ald[d * NH + h];
    a = (a > 0.f) ? a : 0.2f * a;
    g_ealpha[idx] = a;
    atomicMax(&g_menc[d * NH + h], fenc(a));
}

// ---------------- edge pass 2: exp + denominator ----------------
__global__ void k_edge_exp(const int* __restrict__ ei) {
    int idx = blockIdx.x * blockDim.x + threadIdx.x;
    if (idx >= ESL * NH) return;
    int e = idx >> 2, h = idx & 3;
    int d = (e < EE) ? ei[EE + e] : (e - EE);
    float a = g_ealpha[idx];
    float m = fdec(g_menc[d * NH + h]);
    float ex = expf(a - m);
    g_ealpha[idx] = ex;
    atomicAdd(&g_den[d * NH + h], ex);
}

// ---------------- edge pass 3: weighted scatter-sum (warp per edge, v4 red) ----------------
__global__ void k_agg(const int* __restrict__ ei) {
    int gw = (blockIdx.x * blockDim.x + threadIdx.x) >> 5;
    int lane = threadIdx.x & 31;
    if (gw >= ESL) return;
    int s = (gw < EE) ? ei[gw] : (gw - EE);
    int d = (gw < EE) ? ei[EE + gw] : (gw - EE);
    float c0 = g_ealpha[(size_t)gw * NH + 0] / (g_den[d * NH + 0] + 1e-16f);
    float c1 = g_ealpha[(size_t)gw * NH + 1] / (g_den[d * NH + 1] + 1e-16f);
    float c2 = g_ealpha[(size_t)gw * NH + 2] / (g_den[d * NH + 2] + 1e-16f);
    float c3 = g_ealpha[(size_t)gw * NH + 3] / (g_den[d * NH + 3] + 1e-16f);
    const float4* xr = (const float4*)(g_xp + (size_t)s * HH);
    float* ar = g_agg + (size_t)d * HH;
    float cfa = (lane < 16) ? c0 : c1;
    float cfb = (lane < 16) ? c2 : c3;
    float4 v0 = xr[lane];
    float4 v1 = xr[lane + 32];
    red4(&ar[lane * 4], v0.x * cfa, v0.y * cfa, v0.z * cfa, v0.w * cfa);
    red4(&ar[(lane + 32) * 4], v1.x * cfb, v1.y * cfb, v1.z * cfb, v1.w * cfb);
}

// ---------------- bias + ELU ----------------
__global__ void k_bias_elu(const float* __restrict__ b, float* __restrict__ out) {
    int idx = blockIdx.x * blockDim.x + threadIdx.x;
    if (idx >= NN * HH) return;
    float v = g_agg[idx] + b[idx & (HH - 1)];
    out[idx] = (v > 0.f) ? v : expm1f(v);
}

// ---------------- edge bilinear: warp per edge ----------------
__global__ void k_edge_bilinear(const int* __restrict__ ei, const float* __restrict__ h2,
                                const float* __restrict__ bb, float* __restrict__ out_edge) {
    int gw = (blockIdx.x * blockDim.x + threadIdx.x) >> 5;
    int lane = threadIdx.x & 31;
    if (gw >= EE) return;
    int s = ei[gw];
    int d = ei[EE + gw];
    const float4* hd4 = (const float4*)(h2 + (size_t)d * HH);
    float4 hv0 = hd4[lane];
    float4 hv1 = hd4[lane + 32];
    const float4* tp = (const float4*)(g_t + (size_t)s * (OUTE * HH));
    float res0 = 0.f, res1 = 0.f, res2 = 0.f, res3 = 0.f;
#pragma unroll
    for (int o = 0; o < OUTE; o++) {
        float4 t0 = tp[o * 64 + lane];
        float4 t1 = tp[o * 64 + lane + 32];
        float acc = t0.x * hv0.x + t0.y * hv0.y + t0.z * hv0.z + t0.w * hv0.w
                  + t1.x * hv1.x + t1.y * hv1.y + t1.z * hv1.z + t1.w * hv1.w;
#pragma unroll
        for (int off = 16; off > 0; off >>= 1)
            acc += __shfl_xor_sync(0xffffffffu, acc, off);
        if (o == 0) res0 = acc; else if (o == 1) res1 = acc; else if (o == 2) res2 = acc; else res3 = acc;
    }
    if (lane < 4) {
        float r = (lane == 0) ? res0 : (lane == 1) ? res1 : (lane == 2) ? res2 : res3;
        out_edge[(size_t)gw * OUTE + lane] = r + bb[lane];
    }
}

// ---------------- host ----------------
extern "C" void kernel_launch(void* const* d_in, const int* in_sizes, int n_in,
                              void* d_out, int out_size) {
    const float* x   = (const float*)d_in[0];
    const int*   ei  = (const int*)d_in[1];
    const float* W1  = (const float*)d_in[2];
    const float* as1 = (const float*)d_in[3];
    const float* ad1 = (const float*)d_in[4];
    const float* b1  = (const float*)d_in[5];
    const float* W2  = (const float*)d_in[6];
    const float* as2 = (const float*)d_in[7];
    const float* ad2 = (const float*)d_in[8];
    const float* b2  = (const float*)d_in[9];
    const float* Wn  = (const float*)d_in[10];
    const float* bn  = (const float*)d_in[11];
    const float* Wb  = (const float*)d_in[12];
    const float* bb  = (const float*)d_in[13];

    float* out_node = (float*)d_out;
    float* out_edge = out_node + (size_t)NN * OUTN;
    float* out_h    = out_edge + (size_t)EE * OUTE;

    float *p_xp, *p_h1, *p_t, *p_agg;
    __nv_bfloat16 *p_a3, *p_b3;
    cudaGetSymbolAddress((void**)&p_xp, g_xp);
    cudaGetSymbolAddress((void**)&p_h1, g_h1);
    cudaGetSymbolAddress((void**)&p_t, g_t);
    cudaGetSymbolAddress((void**)&p_agg, g_agg);
    cudaGetSymbolAddress((void**)&p_a3, g_a3);
    cudaGetSymbolAddress((void**)&p_b3, g_b3);

    dim3 blk(256);
    int g_elem  = (NN * HH + 255) / 256;
    int g_edge4 = (ESL * NH + 255) / 256;
    int g_aggw  = (ESL + 7) / 8;
    int g_al    = (NN * NH + 255) / 256;

    // ---- layer 1: xp = x @ W1^T (3-term bf16-split tensor core) ----
    k_split3<<<(NN * INCH + 255) / 256, blk>>>(x, p_a3, NN, INCH);
    k_wsplit3<<<(HH * INCH + 255) / 256, blk>>>(W1, p_b3, HH, INCH);
    {
        dim3 grid(HH / 64, (NN + 127) / 128);
        gemm_bf16_nt<<<grid, blk>>>(p_a3, p_b3, p_xp, NN, HH, 3 * INCH);
    }
    k_al<<<g_al, blk>>>(as1, ad1);
    cudaMemsetAsync(p_agg, 0, (size_t)NN * HH * sizeof(float));
    k_init_md<<<g_al, blk>>>();
    k_edge_max<<<g_edge4, blk>>>(ei);
    k_edge_exp<<<g_edge4, blk>>>(ei);
    k_agg<<<g_aggw, blk>>>(ei);
    k_bias_elu<<<g_elem, blk>>>(b1, p_h1);

    // ---- layer 2: xp = h1 @ W2^T ----
    k_split3<<<(NN * HH + 255) / 256, blk>>>(p_h1, p_a3, NN, HH);
    k_wsplit3<<<(HH * HH + 255) / 256, blk>>>(W2, p_b3, HH, HH);
    {
        dim3 grid(HH / 64, (NN + 127) / 128);
        gemm_bf16_nt<<<grid, blk>>>(p_a3, p_b3, p_xp, NN, HH, 3 * HH);
    }
    k_al<<<g_al, blk>>>(as2, ad2);
    cudaMemsetAsync(p_agg, 0, (size_t)NN * HH * sizeof(float));
    k_init_md<<<g_al, blk>>>();
    k_edge_max<<<g_edge4, blk>>>(ei);
    k_edge_exp<<<g_edge4, blk>>>(ei);
    k_agg<<<g_aggw, blk>>>(ei);
    k_bias_elu<<<g_elem, blk>>>(b2, out_h);

    // ---- node predictor (small, fp32 SIMT) ----
    {
        dim3 grid((OUTN + 63) / 64, (NN + 63) / 64);
        sgemm_nt<<<grid, blk>>>(out_h, Wn, out_node, bn, NN, OUTN, HH);
    }

    // ---- edge bilinear: t = h @ WbT (tensor core), then per-edge dot ----
    k_wbt_split3<<<(OUTE * HH * HH + 255) / 256, blk>>>(Wb);
    k_split3<<<(NN * HH + 255) / 256, blk>>>(out_h, p_a3, NN, HH);
    {
        dim3 grid((OUTE * HH) / 64, (NN + 127) / 128);
        gemm_bf16_nt<<<grid, blk>>>(p_a3, p_b3, p_t, NN, OUTE * HH, 3 * HH);
    }
    k_edge_bilinear<<<(EE + 7) / 8, blk>>>(ei, out_h, bb, out_edge);
}

// round 4
// speedup vs baseline: 2.0230x; 1.0705x over previous
#include <cuda_runtime.h>
#include <cuda_bf16.h>
#include <math.h>

#define NN   50000
#define EE   800000
#define ESL  (EE + NN)
#define INCH 128
#define HID  64
#define NH   4
#define HH   256
#define OUTN 16
#define OUTE 4

// ---------------- scratch (__device__ globals: allocation-free rule) ----------------
__device__ float         g_xp[(size_t)NN * HH];
__device__ float         g_h1[(size_t)NN * HH];
__device__ float         g_als[NN * NH];
__device__ float         g_ald[NN * NH];
__device__ float         g_ealpha[(size_t)ESL * NH];
__device__ float         g_t[(size_t)NN * OUTE * HH];          // [N, 1024]
__device__ __nv_bfloat16 g_a3[(size_t)NN * (3 * HH)];          // 3-way split activations
__device__ __nv_bfloat16 g_b3[(size_t)(OUTE * HH) * (3 * HH)]; // 3-way split weights
// CSR scratch
__device__ int g_cntd[NN], g_offd[NN + 1], g_curd[NN], g_srcd[ESL];
__device__ int g_cnts[NN], g_offs[NN + 1], g_curs[NN], g_dsts[EE], g_oids[EE];

// ---------------- helpers ----------------
__device__ __forceinline__ void ldsm_x4(unsigned &r0, unsigned &r1, unsigned &r2, unsigned &r3, unsigned addr) {
    asm volatile("ldmatrix.sync.aligned.m8n8.x4.shared.b16 {%0,%1,%2,%3}, [%4];"
                 : "=r"(r0), "=r"(r1), "=r"(r2), "=r"(r3) : "r"(addr));
}
__device__ __forceinline__ void mma_bf16(float &c0, float &c1, float &c2, float &c3,
                                         unsigned a0, unsigned a1, unsigned a2, unsigned a3,
                                         unsigned b0, unsigned b1) {
    asm volatile("mma.sync.aligned.m16n8k16.row.col.f32.bf16.bf16.f32 "
                 "{%0,%1,%2,%3}, {%4,%5,%6,%7}, {%8,%9}, {%0,%1,%2,%3};"
                 : "+f"(c0), "+f"(c1), "+f"(c2), "+f"(c3)
                 : "r"(a0), "r"(a1), "r"(a2), "r"(a3), "r"(b0), "r"(b1));
}
__device__ __forceinline__ void cp16(unsigned dst, const void* src) {
    asm volatile("cp.async.cg.shared.global [%0], [%1], 16;" :: "r"(dst), "l"(src));
}
__device__ __forceinline__ unsigned pack_bf16(float a, float b) {
    __nv_bfloat162 t = __floats2bfloat162_rn(a, b);
    return *(unsigned*)&t;
}

// ---------------- CSR build ----------------
__global__ void k_hist(const int* __restrict__ ei) {
    int idx = blockIdx.x * blockDim.x + threadIdx.x;
    if (idx >= ESL) return;
    int d = (idx < EE) ? ei[EE + idx] : (idx - EE);
    atomicAdd(&g_cntd[d], 1);
    if (idx < EE) atomicAdd(&g_cnts[ei[idx]], 1);
}

__global__ void k_scan2() {
    int* cnt = blockIdx.x ? g_cnts : g_cntd;
    int* off = blockIdx.x ? g_offs : g_offd;
    int* cur = blockIdx.x ? g_curs : g_curd;
    __shared__ int part[1024];
    int tid = threadIdx.x;
    const int per = (NN + 1023) / 1024;
    int lo = tid * per, hi = min(lo + per, NN);
    int s = 0;
    for (int i = lo; i < hi; i++) s += cnt[i];
    part[tid] = s;
    __syncthreads();
    for (int d = 1; d < 1024; d <<= 1) {
        int v = (tid >= d) ? part[tid - d] : 0;
        __syncthreads();
        part[tid] += v;
        __syncthreads();
    }
    int run = tid ? part[tid - 1] : 0;
    for (int i = lo; i < hi; i++) { off[i] = run; cur[i] = run; run += cnt[i]; }
    if (tid == 1023) off[NN] = part[1023];
}

__global__ void k_scatter(const int* __restrict__ ei) {
    int idx = blockIdx.x * blockDim.x + threadIdx.x;
    if (idx >= ESL) return;
    int s = (idx < EE) ? ei[idx] : (idx - EE);
    int d = (idx < EE) ? ei[EE + idx] : (idx - EE);
    int pos = atomicAdd(&g_curd[d], 1);
    g_srcd[pos] = s;
    if (idx < EE) {
        int p2 = atomicAdd(&g_curs[s], 1);
        g_dsts[p2] = d;
        g_oids[p2] = idx;
    }
}

// ---------------- 3-way split fp32 -> bf16, out layout [R, 3K] = [hi | lo | hi] ----------------
__global__ void k_split3(const float* __restrict__ in, __nv_bfloat16* __restrict__ out, int R, int K) {
    int idx = blockIdx.x * blockDim.x + threadIdx.x;
    if (idx >= R * K) return;
    int r = idx / K, k = idx - r * K;
    float v = in[idx];
    __nv_bfloat16 hi = __float2bfloat16(v);
    float lo = v - __bfloat162float(hi);
    size_t base = (size_t)r * (3 * K);
    out[base + k] = hi;
    out[base + K + k] = __float2bfloat16(lo);
    out[base + 2 * K + k] = hi;
}

// fp32 weights W[R,K] -> split rows [b_hi | b_hi | b_lo]
__global__ void k_wsplit3(const float* __restrict__ W, __nv_bfloat16* __restrict__ out, int R, int K) {
    int idx = blockIdx.x * blockDim.x + threadIdx.x;
    if (idx >= R * K) return;
    int r = idx / K, k = idx - r * K;
    float v = W[idx];
    __nv_bfloat16 hi = __float2bfloat16(v);
    float lo = v - __bfloat162float(hi);
    size_t base = (size_t)r * (3 * K);
    out[base + k] = hi;
    out[base + K + k] = hi;
    out[base + 2 * K + k] = __float2bfloat16(lo);
}

// Wb[o,i,j] -> split-transposed row (o*HH+j): [hi(i) | hi(i) | lo(i)]
__global__ void k_wbt_split3(const float* __restrict__ Wb) {
    int idx = blockIdx.x * blockDim.x + threadIdx.x;
    if (idx >= OUTE * HH * HH) return;
    int o = idx / (HH * HH);
    int i = (idx / HH) % HH;
    int j = idx % HH;
    float v = Wb[idx];
    __nv_bfloat16 hi = __float2bfloat16(v);
    float lo = v - __bfloat162float(hi);
    size_t base = ((size_t)o * HH + j) * (3 * HH);
    g_b3[base + i] = hi;
    g_b3[base + HH + i] = hi;
    g_b3[base + 2 * HH + i] = __float2bfloat16(lo);
}

// ---------------- bf16 tensor-core GEMM: C[M,Nc] = A[M,K2] * B[Nc,K2]^T ----------------
__global__ void __launch_bounds__(256) gemm_bf16_nt(const __nv_bfloat16* __restrict__ A,
                                                    const __nv_bfloat16* __restrict__ B,
                                                    float* __restrict__ C,
                                                    int M, int Nc, int K2) {
    __shared__ __nv_bfloat16 As[2][128 * 32];
    __shared__ __nv_bfloat16 Bs[2][64 * 32];
    const int tid = threadIdx.x;
    const int wid = tid >> 5, lane = tid & 31;
    const int bm = blockIdx.y * 128, bn = blockIdx.x * 64;
    const int wm = (wid >> 1) * 32, wn = (wid & 1) * 32;

    const unsigned as_base = (unsigned)__cvta_generic_to_shared(&As[0][0]);
    const unsigned bs_base = (unsigned)__cvta_generic_to_shared(&Bs[0][0]);

    float acc[2][4][4];
#pragma unroll
    for (int i = 0; i < 2; i++)
#pragma unroll
        for (int j = 0; j < 4; j++)
#pragma unroll
            for (int k = 0; k < 4; k++) acc[i][j][k] = 0.f;

    const int KT = K2 >> 5;
    const int aq0_row = tid >> 2,         aq0_c = tid & 3;
    const int aq1_row = (tid + 256) >> 2, aq1_c = tid & 3;
    const int bq_row = tid >> 2,          bq_c = tid & 3;

#define SWZ(row, c) (((row) * 4 + ((c) ^ (((row) >> 1) & 3))) * 16)

    auto load_stage = [&](int kt, int s) {
        const int k0 = kt * 32;
        const unsigned as_s = as_base + s * 8192;
        const unsigned bs_s = bs_base + s * 4096;
        {
            int gr = bm + aq0_row;
            unsigned dst = as_s + SWZ(aq0_row, aq0_c);
            if (gr < M) cp16(dst, A + (size_t)gr * K2 + k0 + aq0_c * 8);
            else { uint4 z = {0,0,0,0}; *(uint4*)&As[s][(size_t)(SWZ(aq0_row, aq0_c) >> 1)] = z; }
        }
        {
            int gr = bm + aq1_row;
            unsigned dst = as_s + SWZ(aq1_row, aq1_c);
            if (gr < M) cp16(dst, A + (size_t)gr * K2 + k0 + aq1_c * 8);
            else { uint4 z = {0,0,0,0}; *(uint4*)&As[s][(size_t)(SWZ(aq1_row, aq1_c) >> 1)] = z; }
        }
        {
            int gn = bn + bq_row;
            unsigned dst = bs_s + SWZ(bq_row, bq_c);
            if (gn < Nc) cp16(dst, B + (size_t)gn * K2 + k0 + bq_c * 8);
            else { uint4 z = {0,0,0,0}; *(uint4*)&Bs[s][(size_t)(SWZ(bq_row, bq_c) >> 1)] = z; }
        }
        asm volatile("cp.async.commit_group;");
    };

    load_stage(0, 0);
    for (int kt = 0; kt < KT; kt++) {
        const int s = kt & 1;
        asm volatile("cp.async.wait_group 0;");
        __syncthreads();
        if (kt + 1 < KT) load_stage(kt + 1, (kt + 1) & 1);

        const unsigned as_s = as_base + s * 8192;
        const unsigned bs_s = bs_base + s * 4096;
#pragma unroll
        for (int ks = 0; ks < 2; ks++) {
            unsigned a[2][4], b[2][4];
            const int kc = ks * 2 + (lane >> 4);
#pragma unroll
            for (int mf = 0; mf < 2; mf++) {
                int row = wm + mf * 16 + (lane & 15);
                ldsm_x4(a[mf][0], a[mf][1], a[mf][2], a[mf][3], as_s + SWZ(row, kc));
            }
#pragma unroll
            for (int nf2 = 0; nf2 < 2; nf2++) {
                int row = wn + nf2 * 16 + (lane & 15);
                ldsm_x4(b[nf2][0], b[nf2][1], b[nf2][2], b[nf2][3], bs_s + SWZ(row, kc));
            }
#pragma unroll
            for (int mf = 0; mf < 2; mf++)
#pragma unroll
                for (int nf = 0; nf < 4; nf++) {
                    int nf2 = nf >> 1, w = nf & 1;
                    mma_bf16(acc[mf][nf][0], acc[mf][nf][1], acc[mf][nf][2], acc[mf][nf][3],
                             a[mf][0], a[mf][1], a[mf][2], a[mf][3],
                             b[nf2][w], b[nf2][w + 2]);
                }
        }
        __syncthreads();
    }
#undef SWZ

#pragma unroll
    for (int mf = 0; mf < 2; mf++)
#pragma unroll
        for (int nf = 0; nf < 4; nf++) {
            int r0 = bm + wm + mf * 16 + (lane >> 2);
            int c0 = bn + wn + nf * 8 + (lane & 3) * 2;
            if (c0 < Nc) {
                if (r0 < M) {
                    float2 v = {acc[mf][nf][0], acc[mf][nf][1]};
                    *(float2*)&C[(size_t)r0 * Nc + c0] = v;
                }
                if (r0 + 8 < M) {
                    float2 v = {acc[mf][nf][2], acc[mf][nf][3]};
                    *(float2*)&C[(size_t)(r0 + 8) * Nc + c0] = v;
                }
            }
        }
}

// ---------------- fp32 SGEMM (small node predictor) ----------------
__global__ void sgemm_nt(const float* __restrict__ A, const float* __restrict__ B,
                         float* __restrict__ C, const float* __restrict__ bias,
                         int M, int Nc, int K) {
    __shared__ float As[16][68];
    __shared__ float Bs[16][68];
    int tx = threadIdx.x & 15;
    int ty = threadIdx.x >> 4;
    int bm = blockIdx.y * 64;
    int bn = blockIdx.x * 64;

    float acc[4][4] = {};
    for (int k0 = 0; k0 < K; k0 += 16) {
        for (int i = threadIdx.x; i < 64 * 16; i += 256) {
            int r = i >> 4, c = i & 15;
            int gr = bm + r;
            As[c][r] = (gr < M) ? A[(size_t)gr * K + k0 + c] : 0.f;
        }
        for (int i = threadIdx.x; i < 64 * 16; i += 256) {
            int r = i >> 4, c = i & 15;
            int gn = bn + r;
            Bs[c][r] = (gn < Nc) ? B[(size_t)gn * K + k0 + c] : 0.f;
        }
        __syncthreads();
#pragma unroll
        for (int kk = 0; kk < 16; kk++) {
            float4 a4 = *(const float4*)&As[kk][ty * 4];
            float4 b4 = *(const float4*)&Bs[kk][tx * 4];
            float a[4] = {a4.x, a4.y, a4.z, a4.w};
            float b[4] = {b4.x, b4.y, b4.z, b4.w};
#pragma unroll
            for (int i = 0; i < 4; i++)
#pragma unroll
                for (int j = 0; j < 4; j++) acc[i][j] = fmaf(a[i], b[j], acc[i][j]);
        }
        __syncthreads();
    }
#pragma unroll
    for (int i = 0; i < 4; i++) {
        int gm = bm + ty * 4 + i;
        if (gm >= M) continue;
#pragma unroll
        for (int j = 0; j < 4; j++) {
            int gn = bn + tx * 4 + j;
            if (gn < Nc) {
                float v = acc[i][j];
                if (bias) v += bias[gn];
                C[(size_t)gm * Nc + gn] = v;
            }
        }
    }
}

// ---------------- attention logits: warp per node, coalesced ----------------
__global__ void k_al(const float* __restrict__ a_s, const float* __restrict__ a_d) {
    int n = (blockIdx.x * blockDim.x + threadIdx.x) >> 5;
    int lane = threadIdx.x & 31;
    if (n >= NN) return;
    int hb = lane >> 3, w = lane & 7;
    const float4* xr = (const float4*)(g_xp + (size_t)n * HH);
    float4 v0 = xr[hb * 16 + w * 2];
    float4 v1 = xr[hb * 16 + w * 2 + 1];
    const float4* as4 = (const float4*)a_s;
    const float4* ad4 = (const float4*)a_d;
    float4 s0 = __ldg(&as4[hb * 16 + w * 2]), s1 = __ldg(&as4[hb * 16 + w * 2 + 1]);
    float4 d0 = __ldg(&ad4[hb * 16 + w * 2]), d1 = __ldg(&ad4[hb * 16 + w * 2 + 1]);
    float ps = v0.x * s0.x + v0.y * s0.y + v0.z * s0.z + v0.w * s0.w
             + v1.x * s1.x + v1.y * s1.y + v1.z * s1.z + v1.w * s1.w;
    float pd = v0.x * d0.x + v0.y * d0.y + v0.z * d0.z + v0.w * d0.w
             + v1.x * d1.x + v1.y * d1.y + v1.z * d1.z + v1.w * d1.w;
#pragma unroll
    for (int off = 1; off < 8; off <<= 1) {
        ps += __shfl_xor_sync(0xffffffffu, ps, off);
        pd += __shfl_xor_sync(0xffffffffu, pd, off);
    }
    if (w == 0) {
        g_als[n * NH + hb] = ps;
        g_ald[n * NH + hb] = pd;
    }
}

// ---------------- fused GAT aggregation: warp per dst node ----------------
// Phase A: per-edge alpha + online softmax (m, den). Phase B: weighted gather.
// Epilogue: bias + ELU + fp32 store + bf16 3-way split store.
__global__ void k_gat(const float* __restrict__ bias, float* __restrict__ outh,
                      __nv_bfloat16* __restrict__ a3out) {
    int n = (blockIdx.x * blockDim.x + threadIdx.x) >> 5;
    int lane = threadIdx.x & 31;
    if (n >= NN) return;
    int start = g_offd[n], end = g_offd[n + 1];

    // phase A: lane handles edges start+q (stride 8) for head h
    int h = lane & 3, q = lane >> 2;
    float ald_h = g_ald[n * NH + h];
    float m = -1e30f, den = 0.f;
    for (int j = start + q; j < end; j += 8) {
        int s = g_srcd[j];
        float a = g_als[s * NH + h] + ald_h;
        a = (a > 0.f) ? a : 0.2f * a;
        g_ealpha[(size_t)j * NH + h] = a;
        if (a > m) { den = den * expf(m - a) + 1.f; m = a; }
        else den += expf(a - m);
    }
#pragma unroll
    for (int off = 4; off < 32; off <<= 1) {
        float mo = __shfl_xor_sync(0xffffffffu, m, off);
        float dn = __shfl_xor_sync(0xffffffffu, den, off);
        float mn = fmaxf(m, mo);
        den = den * expf(m - mn) + dn * expf(mo - mn);
        m = mn;
    }
    __syncwarp();

    // phase B: lane covers channels [lane*8, lane*8+8), head hb = lane>>3
    int hb = lane >> 3;
    float mB = __shfl_sync(0xffffffffu, m, hb);
    float dB = __shfl_sync(0xffffffffu, den, hb);
    float inv = 1.f / (dB + 1e-16f);
    float4 a0 = {0, 0, 0, 0}, a1 = {0, 0, 0, 0};
    for (int j = start; j < end; j++) {
        int s = g_srcd[j];
        float al = g_ealpha[(size_t)j * NH + hb];
        float coef = expf(al - mB) * inv;
        const float4* xr = (const float4*)(g_xp + (size_t)s * HH);
        float4 v0 = xr[lane * 2], v1 = xr[lane * 2 + 1];
        a0.x += v0.x * coef; a0.y += v0.y * coef; a0.z += v0.z * coef; a0.w += v0.w * coef;
        a1.x += v1.x * coef; a1.y += v1.y * coef; a1.z += v1.z * coef; a1.w += v1.w * coef;
    }

    // epilogue: bias + ELU
    const float4* b4 = (const float4*)bias;
    float4 bb0 = __ldg(&b4[lane * 2]), bb1 = __ldg(&b4[lane * 2 + 1]);
    float v[8];
    v[0] = a0.x + bb0.x; v[1] = a0.y + bb0.y; v[2] = a0.z + bb0.z; v[3] = a0.w + bb0.w;
    v[4] = a1.x + bb1.x; v[5] = a1.y + bb1.y; v[6] = a1.z + bb1.z; v[7] = a1.w + bb1.w;
#pragma unroll
    for (int i = 0; i < 8; i++) v[i] = (v[i] > 0.f) ? v[i] : expm1f(v[i]);

    float4* orow = (float4*)(outh + (size_t)n * HH);
    float4 o0 = {v[0], v[1], v[2], v[3]}, o1 = {v[4], v[5], v[6], v[7]};
    orow[lane * 2] = o0;
    orow[lane * 2 + 1] = o1;

    // bf16 3-way split: [hi(256) | lo(256) | hi(256)]
    unsigned hi_p[4], lo_p[4];
    float hif[8];
#pragma unroll
    for (int i = 0; i < 8; i++) {
        __nv_bfloat16 hb16 = __float2bfloat16(v[i]);
        hif[i] = __bfloat162float(hb16);
    }
#pragma unroll
    for (int i = 0; i < 4; i++) {
        hi_p[i] = pack_bf16(hif[2 * i], hif[2 * i + 1]);
        lo_p[i] = pack_bf16(v[2 * i] - hif[2 * i], v[2 * i + 1] - hif[2 * i + 1]);
    }
    __nv_bfloat16* arow = a3out + (size_t)n * (3 * HH);
    uint4 hv = {hi_p[0], hi_p[1], hi_p[2], hi_p[3]};
    uint4 lv = {lo_p[0], lo_p[1], lo_p[2], lo_p[3]};
    ((uint4*)(arow))[lane] = hv;
    ((uint4*)(arow + HH))[lane] = lv;
    ((uint4*)(arow + 2 * HH))[lane] = hv;
}

// ---------------- edge bilinear: warp per src node (src-CSR), t in registers ----------------
__global__ void k_bil(const float* __restrict__ h2, const float* __restrict__ bb,
                      float* __restrict__ out_edge) {
    int n = (blockIdx.x * blockDim.x + threadIdx.x) >> 5;
    int lane = threadIdx.x & 31;
    if (n >= NN) return;
    int start = g_offs[n], end = g_offs[n + 1];
    if (start == end) return;

    const float4* tp = (const float4*)(g_t + (size_t)n * (OUTE * HH));
    float4 t0[OUTE], t1[OUTE];
#pragma unroll
    for (int o = 0; o < OUTE; o++) {
        t0[o] = tp[o * 64 + lane * 2];
        t1[o] = tp[o * 64 + lane * 2 + 1];
    }
    float myb = (lane < OUTE) ? __ldg(&bb[lane]) : 0.f;

    for (int j = start; j < end; j++) {
        int d = g_dsts[j];
        int orig = g_oids[j];
        const float4* hr = (const float4*)(h2 + (size_t)d * HH);
        float4 v0 = hr[lane * 2], v1 = hr[lane * 2 + 1];
        float p[OUTE];
#pragma unroll
        for (int o = 0; o < OUTE; o++)
            p[o] = t0[o].x * v0.x + t0[o].y * v0.y + t0[o].z * v0.z + t0[o].w * v0.w
                 + t1[o].x * v1.x + t1[o].y * v1.y + t1[o].z * v1.z + t1[o].w * v1.w;
#pragma unroll
        for (int off = 16; off > 0; off >>= 1)
#pragma unroll
            for (int o = 0; o < OUTE; o++)
                p[o] += __shfl_xor_sync(0xffffffffu, p[o], off);
        if (lane < OUTE) {
            float r = (lane == 0) ? p[0] : (lane == 1) ? p[1] : (lane == 2) ? p[2] : p[3];
            out_edge[(size_t)orig * OUTE + lane] = r + myb;
        }
    }
}

// ---------------- host ----------------
extern "C" void kernel_launch(void* const* d_in, const int* in_sizes, int n_in,
                              void* d_out, int out_size) {
    const float* x   = (const float*)d_in[0];
    const int*   ei  = (const int*)d_in[1];
    const float* W1  = (const float*)d_in[2];
    const float* as1 = (const float*)d_in[3];
    const float* ad1 = (const float*)d_in[4];
    const float* b1  = (const float*)d_in[5];
    const float* W2  = (const float*)d_in[6];
    const float* as2 = (const float*)d_in[7];
    const float* ad2 = (const float*)d_in[8];
    const float* b2  = (const float*)d_in[9];
    const float* Wn  = (const float*)d_in[10];
    const float* bn  = (const float*)d_in[11];
    const float* Wb  = (const float*)d_in[12];
    const float* bb  = (const float*)d_in[13];

    float* out_node = (float*)d_out;
    float* out_edge = out_node + (size_t)NN * OUTN;
    float* out_h    = out_edge + (size_t)EE * OUTE;

    float *p_xp, *p_h1, *p_t;
    __nv_bfloat16 *p_a3, *p_b3;
    int *p_cntd, *p_cnts;
    cudaGetSymbolAddress((void**)&p_xp, g_xp);
    cudaGetSymbolAddress((void**)&p_h1, g_h1);
    cudaGetSymbolAddress((void**)&p_t, g_t);
    cudaGetSymbolAddress((void**)&p_a3, g_a3);
    cudaGetSymbolAddress((void**)&p_b3, g_b3);
    cudaGetSymbolAddress((void**)&p_cntd, g_cntd);
    cudaGetSymbolAddress((void**)&p_cnts, g_cnts);

    dim3 blk(256);
    int g_nodeW = (NN * 32 + 255) / 256;     // warp-per-node grids
    int g_esl   = (ESL + 255) / 256;

    // ---- CSR build (dst for attention, src for bilinear) ----
    cudaMemsetAsync(p_cntd, 0, NN * sizeof(int));
    cudaMemsetAsync(p_cnts, 0, NN * sizeof(int));
    k_hist<<<g_esl, blk>>>(ei);
    k_scan2<<<2, 1024>>>();
    k_scatter<<<g_esl, blk>>>(ei);

    // ---- layer 1: xp = x @ W1^T ----
    k_split3<<<(NN * INCH + 255) / 256, blk>>>(x, p_a3, NN, INCH);
    k_wsplit3<<<(HH * INCH + 255) / 256, blk>>>(W1, p_b3, HH, INCH);
    {
        dim3 grid(HH / 64, (NN + 127) / 128);
        gemm_bf16_nt<<<grid, blk>>>(p_a3, p_b3, p_xp, NN, HH, 3 * INCH);
    }
    k_al<<<g_nodeW, blk>>>(as1, ad1);
    k_gat<<<g_nodeW, blk>>>(b1, p_h1, p_a3);   // h1 fp32 + split a3

    // ---- layer 2: xp = h1 @ W2^T ----
    k_wsplit3<<<(HH * HH + 255) / 256, blk>>>(W2, p_b3, HH, HH);
    {
        dim3 grid(HH / 64, (NN + 127) / 128);
        gemm_bf16_nt<<<grid, blk>>>(p_a3, p_b3, p_xp, NN, HH, 3 * HH);
    }
    k_al<<<g_nodeW, blk>>>(as2, ad2);
    k_gat<<<g_nodeW, blk>>>(b2, out_h, p_a3);  // out_h fp32 + split a3

    // ---- node predictor ----
    {
        dim3 grid((OUTN + 63) / 64, (NN + 63) / 64);
        sgemm_nt<<<grid, blk>>>(out_h, Wn, out_node, bn, NN, OUTN, HH);
    }

    // ---- edge bilinear: t = h @ WbT (a3 already holds split of out_h) ----
    k_wbt_split3<<<(OUTE * HH * HH + 255) / 256, blk>>>(Wb);
    {
        dim3 grid((OUTE * HH) / 64, (NN + 127) / 128);
        gemm_bf16_nt<<<grid, blk>>>(p_a3, p_b3, p_t, NN, OUTE * HH, 3 * HH);
    }
    k_bil<<<g_nodeW, blk>>>(out_h, bb, out_edge);
}

// round 7
// speedup vs baseline: 3.0609x; 1.5131x over previous
#include <cuda_runtime.h>
#include <cuda_bf16.h>
#include <math.h>

#define NN   50000
#define EE   800000
#define ESL  (EE + NN)
#define INCH 128
#define HID  64
#define NH   4
#define HH   256
#define OUTN 16
#define OUTE 4

// ---------------- scratch (__device__ globals: allocation-free rule) ----------------
__device__ float         g_xp[(size_t)NN * HH];
__device__ float         g_h1[(size_t)NN * HH];
__device__ float         g_als[NN * NH];
__device__ float         g_ald[NN * NH];
__device__ float         g_ealpha[(size_t)ESL * NH];
__device__ float         g_t[(size_t)NN * OUTE * HH];          // [N, 1024]
__device__ __nv_bfloat16 g_a3[(size_t)NN * (3 * HH)];          // 3-way split activations
__device__ __nv_bfloat16 g_b3[(size_t)(OUTE * HH) * (3 * HH)]; // 3-way split weights
// CSR scratch
__device__ int g_cntd[NN], g_offd[NN + 1], g_curd[NN], g_srcd[ESL];
__device__ int g_cnts[NN], g_offs[NN + 1], g_curs[NN], g_dsts[EE], g_oids[EE];

// ---------------- helpers ----------------
__device__ __forceinline__ void ldsm_x4(unsigned &r0, unsigned &r1, unsigned &r2, unsigned &r3, unsigned addr) {
    asm volatile("ldmatrix.sync.aligned.m8n8.x4.shared.b16 {%0,%1,%2,%3}, [%4];"
                 : "=r"(r0), "=r"(r1), "=r"(r2), "=r"(r3) : "r"(addr));
}
__device__ __forceinline__ void mma_bf16(float &c0, float &c1, float &c2, float &c3,
                                         unsigned a0, unsigned a1, unsigned a2, unsigned a3,
                                         unsigned b0, unsigned b1) {
    asm volatile("mma.sync.aligned.m16n8k16.row.col.f32.bf16.bf16.f32 "
                 "{%0,%1,%2,%3}, {%4,%5,%6,%7}, {%8,%9}, {%0,%1,%2,%3};"
                 : "+f"(c0), "+f"(c1), "+f"(c2), "+f"(c3)
                 : "r"(a0), "r"(a1), "r"(a2), "r"(a3), "r"(b0), "r"(b1));
}
__device__ __forceinline__ void cp16(unsigned dst, const void* src) {
    asm volatile("cp.async.cg.shared.global [%0], [%1], 16;" :: "r"(dst), "l"(src));
}
__device__ __forceinline__ unsigned pack_bf16(float a, float b) {
    __nv_bfloat162 t = __floats2bfloat162_rn(a, b);
    return *(unsigned*)&t;
}

// ---------------- CSR build ----------------
__global__ void k_hist(const int* __restrict__ ei) {
    int idx = blockIdx.x * blockDim.x + threadIdx.x;
    if (idx >= ESL) return;
    int d = (idx < EE) ? ei[EE + idx] : (idx - EE);
    atomicAdd(&g_cntd[d], 1);
    if (idx < EE) atomicAdd(&g_cnts[ei[idx]], 1);
}

__global__ void k_scan2() {
    int* cnt = blockIdx.x ? g_cnts : g_cntd;
    int* off = blockIdx.x ? g_offs : g_offd;
    int* cur = blockIdx.x ? g_curs : g_curd;
    __shared__ int part[1024];
    int tid = threadIdx.x;
    const int per = (NN + 1023) / 1024;
    int lo = tid * per, hi = min(lo + per, NN);
    int s = 0;
    for (int i = lo; i < hi; i++) s += cnt[i];
    part[tid] = s;
    __syncthreads();
    for (int d = 1; d < 1024; d <<= 1) {
        int v = (tid >= d) ? part[tid - d] : 0;
        __syncthreads();
        part[tid] += v;
        __syncthreads();
    }
    int run = tid ? part[tid - 1] : 0;
    for (int i = lo; i < hi; i++) { off[i] = run; cur[i] = run; run += cnt[i]; }
    if (tid == 1023) off[NN] = part[1023];
}

__global__ void k_scatter(const int* __restrict__ ei) {
    int idx = blockIdx.x * blockDim.x + threadIdx.x;
    if (idx >= ESL) return;
    int s = (idx < EE) ? ei[idx] : (idx - EE);
    int d = (idx < EE) ? ei[EE + idx] : (idx - EE);
    int pos = atomicAdd(&g_curd[d], 1);
    g_srcd[pos] = s;
    if (idx < EE) {
        int p2 = atomicAdd(&g_curs[s], 1);
        g_dsts[p2] = d;
        g_oids[p2] = idx;
    }
}

// ---------------- 3-way split fp32 -> bf16, out layout [R, 3K] = [hi | lo | hi] ----------------
__global__ void k_split3(const float* __restrict__ in, __nv_bfloat16* __restrict__ out, int R, int K) {
    int idx = blockIdx.x * blockDim.x + threadIdx.x;
    if (idx >= R * K) return;
    int r = idx / K, k = idx - r * K;
    float v = in[idx];
    __nv_bfloat16 hi = __float2bfloat16(v);
    float lo = v - __bfloat162float(hi);
    size_t base = (size_t)r * (3 * K);
    out[base + k] = hi;
    out[base + K + k] = __float2bfloat16(lo);
    out[base + 2 * K + k] = hi;
}

// fp32 weights W[R,K] -> split rows [b_hi | b_hi | b_lo]
__global__ void k_wsplit3(const float* __restrict__ W, __nv_bfloat16* __restrict__ out, int R, int K) {
    int idx = blockIdx.x * blockDim.x + threadIdx.x;
    if (idx >= R * K) return;
    int r = idx / K, k = idx - r * K;
    float v = W[idx];
    __nv_bfloat16 hi = __float2bfloat16(v);
    float lo = v - __bfloat162float(hi);
    size_t base = (size_t)r * (3 * K);
    out[base + k] = hi;
    out[base + K + k] = hi;
    out[base + 2 * K + k] = __float2bfloat16(lo);
}

// Wb[o,i,j] -> split-transposed row (o*HH+j): [hi(i) | hi(i) | lo(i)]
__global__ void k_wbt_split3(const float* __restrict__ Wb) {
    int idx = blockIdx.x * blockDim.x + threadIdx.x;
    if (idx >= OUTE * HH * HH) return;
    int o = idx / (HH * HH);
    int i = (idx / HH) % HH;
    int j = idx % HH;
    float v = Wb[idx];
    __nv_bfloat16 hi = __float2bfloat16(v);
    float lo = v - __bfloat162float(hi);
    size_t base = ((size_t)o * HH + j) * (3 * HH);
    g_b3[base + i] = hi;
    g_b3[base + HH + i] = hi;
    g_b3[base + 2 * HH + i] = __float2bfloat16(lo);
}

// ---------------- bf16 tensor-core GEMM: C[M,Nc] = A[M,K2] * B[Nc,K2]^T ----------------
// 128x128 block tile, BK=32, 3-stage cp.async pipeline, 8 warps (2x4) of 64x32.
#define SWZ(row, c) (((row) * 4 + ((c) ^ (((row) >> 1) & 3))) * 16)
__global__ void __launch_bounds__(256) gemm_bf16_nt(const __nv_bfloat16* __restrict__ A,
                                                    const __nv_bfloat16* __restrict__ B,
                                                    float* __restrict__ C,
                                                    int M, int Nc, int K2) {
    __shared__ __nv_bfloat16 As[3][128 * 32];
    __shared__ __nv_bfloat16 Bs[3][128 * 32];
    const int tid = threadIdx.x;
    const int wid = tid >> 5, lane = tid & 31;
    const int bm = blockIdx.y * 128, bn = blockIdx.x * 128;
    const int wm = (wid >> 2) * 64, wn = (wid & 3) * 32;

    const unsigned as_base = (unsigned)__cvta_generic_to_shared(&As[0][0]);
    const unsigned bs_base = (unsigned)__cvta_generic_to_shared(&Bs[0][0]);

    float acc[4][4][4];
#pragma unroll
    for (int i = 0; i < 4; i++)
#pragma unroll
        for (int j = 0; j < 4; j++)
#pragma unroll
            for (int k = 0; k < 4; k++) acc[i][j][k] = 0.f;

    const int KT = K2 >> 5;
    const int lrow0 = tid >> 2, lrow1 = (tid >> 2) + 64, lc = tid & 3;

    auto load_stage = [&](int kt, int s) {
        const int k0 = kt * 32;
        const unsigned as_s = as_base + s * 8192;
        const unsigned bs_s = bs_base + s * 8192;
        {
            int gr = bm + lrow0;
            if (gr < M) cp16(as_s + SWZ(lrow0, lc), A + (size_t)gr * K2 + k0 + lc * 8);
            else { uint4 z = {0,0,0,0}; *(uint4*)&As[s][(size_t)(SWZ(lrow0, lc) >> 1)] = z; }
        }
        {
            int gr = bm + lrow1;
            if (gr < M) cp16(as_s + SWZ(lrow1, lc), A + (size_t)gr * K2 + k0 + lc * 8);
            else { uint4 z = {0,0,0,0}; *(uint4*)&As[s][(size_t)(SWZ(lrow1, lc) >> 1)] = z; }
        }
        {
            int gn = bn + lrow0;
            if (gn < Nc) cp16(bs_s + SWZ(lrow0, lc), B + (size_t)gn * K2 + k0 + lc * 8);
            else { uint4 z = {0,0,0,0}; *(uint4*)&Bs[s][(size_t)(SWZ(lrow0, lc) >> 1)] = z; }
        }
        {
            int gn = bn + lrow1;
            if (gn < Nc) cp16(bs_s + SWZ(lrow1, lc), B + (size_t)gn * K2 + k0 + lc * 8);
            else { uint4 z = {0,0,0,0}; *(uint4*)&Bs[s][(size_t)(SWZ(lrow1, lc) >> 1)] = z; }
        }
        asm volatile("cp.async.commit_group;");
    };

    load_stage(0, 0);
    load_stage(1, 1);
    for (int kt = 0; kt < KT; kt++) {
        const int s = kt % 3;
        asm volatile("cp.async.wait_group 1;");
        __syncthreads();
        if (kt + 2 < KT) load_stage(kt + 2, (kt + 2) % 3);

        const unsigned as_s = as_base + s * 8192;
        const unsigned bs_s = bs_base + s * 8192;
#pragma unroll
        for (int ks = 0; ks < 2; ks++) {
            unsigned a[4][4], b[2][4];
            const int kc = ks * 2 + (lane >> 4);
#pragma unroll
            for (int mf = 0; mf < 4; mf++) {
                int row = wm + mf * 16 + (lane & 15);
                ldsm_x4(a[mf][0], a[mf][1], a[mf][2], a[mf][3], as_s + SWZ(row, kc));
            }
#pragma unroll
            for (int nf2 = 0; nf2 < 2; nf2++) {
                int row = wn + nf2 * 16 + (lane & 15);
                ldsm_x4(b[nf2][0], b[nf2][1], b[nf2][2], b[nf2][3], bs_s + SWZ(row, kc));
            }
#pragma unroll
            for (int mf = 0; mf < 4; mf++)
#pragma unroll
                for (int nf = 0; nf < 4; nf++) {
                    int nf2 = nf >> 1, w = nf & 1;
                    mma_bf16(acc[mf][nf][0], acc[mf][nf][1], acc[mf][nf][2], acc[mf][nf][3],
                             a[mf][0], a[mf][1], a[mf][2], a[mf][3],
                             b[nf2][w], b[nf2][w + 2]);
                }
        }
        __syncthreads();
    }

#pragma unroll
    for (int mf = 0; mf < 4; mf++)
#pragma unroll
        for (int nf = 0; nf < 4; nf++) {
            int r0 = bm + wm + mf * 16 + (lane >> 2);
            int c0 = bn + wn + nf * 8 + (lane & 3) * 2;
            if (c0 < Nc) {
                if (r0 < M) {
                    float2 v = {acc[mf][nf][0], acc[mf][nf][1]};
                    *(float2*)&C[(size_t)r0 * Nc + c0] = v;
                }
                if (r0 + 8 < M) {
                    float2 v = {acc[mf][nf][2], acc[mf][nf][3]};
                    *(float2*)&C[(size_t)(r0 + 8) * Nc + c0] = v;
                }
            }
        }
}
#undef SWZ

// ---------------- fp32 SGEMM (small node predictor) ----------------
__global__ void sgemm_nt(const float* __restrict__ A, const float* __restrict__ B,
                         float* __restrict__ C, const float* __restrict__ bias,
                         int M, int Nc, int K) {
    __shared__ float As[16][68];
    __shared__ float Bs[16][68];
    int tx = threadIdx.x & 15;
    int ty = threadIdx.x >> 4;
    int bm = blockIdx.y * 64;
    int bn = blockIdx.x * 64;

    float acc[4][4] = {};
    for (int k0 = 0; k0 < K; k0 += 16) {
        for (int i = threadIdx.x; i < 64 * 16; i += 256) {
            int r = i >> 4, c = i & 15;
            int gr = bm + r;
            As[c][r] = (gr < M) ? A[(size_t)gr * K + k0 + c] : 0.f;
        }
        for (int i = threadIdx.x; i < 64 * 16; i += 256) {
            int r = i >> 4, c = i & 15;
            int gn = bn + r;
            Bs[c][r] = (gn < Nc) ? B[(size_t)gn * K + k0 + c] : 0.f;
        }
        __syncthreads();
#pragma unroll
        for (int kk = 0; kk < 16; kk++) {
            float4 a4 = *(const float4*)&As[kk][ty * 4];
            float4 b4 = *(const float4*)&Bs[kk][tx * 4];
            float a[4] = {a4.x, a4.y, a4.z, a4.w};
            float b[4] = {b4.x, b4.y, b4.z, b4.w};
#pragma unroll
            for (int i = 0; i < 4; i++)
#pragma unroll
                for (int j = 0; j < 4; j++) acc[i][j] = fmaf(a[i], b[j], acc[i][j]);
        }
        __syncthreads();
    }
#pragma unroll
    for (int i = 0; i < 4; i++) {
        int gm = bm + ty * 4 + i;
        if (gm >= M) continue;
#pragma unroll
        for (int j = 0; j < 4; j++) {
            int gn = bn + tx * 4 + j;
            if (gn < Nc) {
                float v = acc[i][j];
                if (bias) v += bias[gn];
                C[(size_t)gm * Nc + gn] = v;
            }
        }
    }
}

// ---------------- attention logits: warp per node, coalesced ----------------
__global__ void k_al(const float* __restrict__ a_s, const float* __restrict__ a_d) {
    int n = (blockIdx.x * blockDim.x + threadIdx.x) >> 5;
    int lane = threadIdx.x & 31;
    if (n >= NN) return;
    int hb = lane >> 3, w = lane & 7;
    const float4* xr = (const float4*)(g_xp + (size_t)n * HH);
    float4 v0 = xr[hb * 16 + w * 2];
    float4 v1 = xr[hb * 16 + w * 2 + 1];
    const float4* as4 = (const float4*)a_s;
    const float4* ad4 = (const float4*)a_d;
    float4 s0 = __ldg(&as4[hb * 16 + w * 2]), s1 = __ldg(&as4[hb * 16 + w * 2 + 1]);
    float4 d0 = __ldg(&ad4[hb * 16 + w * 2]), d1 = __ldg(&ad4[hb * 16 + w * 2 + 1]);
    float ps = v0.x * s0.x + v0.y * s0.y + v0.z * s0.z + v0.w * s0.w
             + v1.x * s1.x + v1.y * s1.y + v1.z * s1.z + v1.w * s1.w;
    float pd = v0.x * d0.x + v0.y * d0.y + v0.z * d0.z + v0.w * d0.w
             + v1.x * d1.x + v1.y * d1.y + v1.z * d1.z + v1.w * d1.w;
#pragma unroll
    for (int off = 1; off < 8; off <<= 1) {
        ps += __shfl_xor_sync(0xffffffffu, ps, off);
        pd += __shfl_xor_sync(0xffffffffu, pd, off);
    }
    if (w == 0) {
        g_als[n * NH + hb] = ps;
        g_ald[n * NH + hb] = pd;
    }
}

// ---------------- fused GAT aggregation: warp per dst node ----------------
__global__ void k_gat(const float* __restrict__ bias, float* __restrict__ outh,
                      __nv_bfloat16* __restrict__ a3out) {
    int n = (blockIdx.x * blockDim.x + threadIdx.x) >> 5;
    int lane = threadIdx.x & 31;
    if (n >= NN) return;
    int start = g_offd[n], end = g_offd[n + 1];

    // phase A: lane handles edges start+q (stride 8) for head h
    int h = lane & 3, q = lane >> 2;
    float ald_h = g_ald[n * NH + h];
    float m = -1e30f, den = 0.f;
    for (int j = start + q; j < end; j += 8) {
        int s = g_srcd[j];
        float a = g_als[s * NH + h] + ald_h;
        a = (a > 0.f) ? a : 0.2f * a;
        g_ealpha[(size_t)j * NH + h] = a;
        if (a > m) { den = den * expf(m - a) + 1.f; m = a; }
        else den += expf(a - m);
    }
#pragma unroll
    for (int off = 4; off < 32; off <<= 1) {
        float mo = __shfl_xor_sync(0xffffffffu, m, off);
        float dn = __shfl_xor_sync(0xffffffffu, den, off);
        float mn = fmaxf(m, mo);
        den = den * expf(m - mn) + dn * expf(mo - mn);
        m = mn;
    }
    __syncwarp();

    // phase B: lane covers channels [lane*8, lane*8+8), head hb = lane>>3
    int hb = lane >> 3;
    float mB = __shfl_sync(0xffffffffu, m, hb);
    float dB = __shfl_sync(0xffffffffu, den, hb);
    float inv = 1.f / (dB + 1e-16f);
    float4 a0 = {0, 0, 0, 0}, a1 = {0, 0, 0, 0};
    for (int j = start; j < end; j++) {
        int s = g_srcd[j];
        float al = g_ealpha[(size_t)j * NH + hb];
        float coef = expf(al - mB) * inv;
        const float4* xr = (const float4*)(g_xp + (size_t)s * HH);
        float4 v0 = xr[lane * 2], v1 = xr[lane * 2 + 1];
        a0.x += v0.x * coef; a0.y += v0.y * coef; a0.z += v0.z * coef; a0.w += v0.w * coef;
        a1.x += v1.x * coef; a1.y += v1.y * coef; a1.z += v1.z * coef; a1.w += v1.w * coef;
    }

    // epilogue: bias + ELU
    const float4* b4 = (const float4*)bias;
    float4 bb0 = __ldg(&b4[lane * 2]), bb1 = __ldg(&b4[lane * 2 + 1]);
    float v[8];
    v[0] = a0.x + bb0.x; v[1] = a0.y + bb0.y; v[2] = a0.z + bb0.z; v[3] = a0.w + bb0.w;
    v[4] = a1.x + bb1.x; v[5] = a1.y + bb1.y; v[6] = a1.z + bb1.z; v[7] = a1.w + bb1.w;
#pragma unroll
    for (int i = 0; i < 8; i++) v[i] = (v[i] > 0.f) ? v[i] : expm1f(v[i]);

    float4* orow = (float4*)(outh + (size_t)n * HH);
    float4 o0 = {v[0], v[1], v[2], v[3]}, o1 = {v[4], v[5], v[6], v[7]};
    orow[lane * 2] = o0;
    orow[lane * 2 + 1] = o1;

    // bf16 3-way split: [hi(256) | lo(256) | hi(256)]
    unsigned hi_p[4], lo_p[4];
    float hif[8];
#pragma unroll
    for (int i = 0; i < 8; i++) {
        __nv_bfloat16 hb16 = __float2bfloat16(v[i]);
        hif[i] = __bfloat162float(hb16);
    }
#pragma unroll
    for (int i = 0; i < 4; i++) {
        hi_p[i] = pack_bf16(hif[2 * i], hif[2 * i + 1]);
        lo_p[i] = pack_bf16(v[2 * i] - hif[2 * i], v[2 * i + 1] - hif[2 * i + 1]);
    }
    __nv_bfloat16* arow = a3out + (size_t)n * (3 * HH);
    uint4 hv = {hi_p[0], hi_p[1], hi_p[2], hi_p[3]};
    uint4 lv = {lo_p[0], lo_p[1], lo_p[2], lo_p[3]};
    ((uint4*)(arow))[lane] = hv;
    ((uint4*)(arow + HH))[lane] = lv;
    ((uint4*)(arow + 2 * HH))[lane] = hv;
}

// ---------------- edge bilinear: warp per src node (src-CSR), t in registers ----------------
__global__ void k_bil(const float* __restrict__ h2, const float* __restrict__ bb,
                      float* __restrict__ out_edge) {
    int n = (blockIdx.x * blockDim.x + threadIdx.x) >> 5;
    int lane = threadIdx.x & 31;
    if (n >= NN) return;
    int start = g_offs[n], end = g_offs[n + 1];
    if (start == end) return;

    const float4* tp = (const float4*)(g_t + (size_t)n * (OUTE * HH));
    float4 t0[OUTE], t1[OUTE];
#pragma unroll
    for (int o = 0; o < OUTE; o++) {
        t0[o] = tp[o * 64 + lane * 2];
        t1[o] = tp[o * 64 + lane * 2 + 1];
    }
    float myb = (lane < OUTE) ? __ldg(&bb[lane]) : 0.f;

    for (int j = start; j < end; j++) {
        int d = g_dsts[j];
        int orig = g_oids[j];
        const float4* hr = (const float4*)(h2 + (size_t)d * HH);
        float4 v0 = hr[lane * 2], v1 = hr[lane * 2 + 1];
        float p[OUTE];
#pragma unroll
        for (int o = 0; o < OUTE; o++)
            p[o] = t0[o].x * v0.x + t0[o].y * v0.y + t0[o].z * v0.z + t0[o].w * v0.w
                 + t1[o].x * v1.x + t1[o].y * v1.y + t1[o].z * v1.z + t1[o].w * v1.w;
#pragma unroll
        for (int off = 16; off > 0; off >>= 1)
#pragma unroll
            for (int o = 0; o < OUTE; o++)
                p[o] += __shfl_xor_sync(0xffffffffu, p[o], off);
        if (lane < OUTE) {
            float r = (lane == 0) ? p[0] : (lane == 1) ? p[1] : (lane == 2) ? p[2] : p[3];
            out_edge[(size_t)orig * OUTE + lane] = r + myb;
        }
    }
}

// ---------------- host ----------------
extern "C" void kernel_launch(void* const* d_in, const int* in_sizes, int n_in,
                              void* d_out, int out_size) {
    const float* x   = (const float*)d_in[0];
    const int*   ei  = (const int*)d_in[1];
    const float* W1  = (const float*)d_in[2];
    const float* as1 = (const float*)d_in[3];
    const float* ad1 = (const float*)d_in[4];
    const float* b1  = (const float*)d_in[5];
    const float* W2  = (const float*)d_in[6];
    const float* as2 = (const float*)d_in[7];
    const float* ad2 = (const float*)d_in[8];
    const float* b2  = (const float*)d_in[9];
    const float* Wn  = (const float*)d_in[10];
    const float* bn  = (const float*)d_in[11];
    const float* Wb  = (const float*)d_in[12];
    const float* bb  = (const float*)d_in[13];

    float* out_node = (float*)d_out;
    float* out_edge = out_node + (size_t)NN * OUTN;
    float* out_h    = out_edge + (size_t)EE * OUTE;

    float *p_xp, *p_h1, *p_t;
    __nv_bfloat16 *p_a3, *p_b3;
    int *p_cntd, *p_cnts;
    cudaGetSymbolAddress((void**)&p_xp, g_xp);
    cudaGetSymbolAddress((void**)&p_h1, g_h1);
    cudaGetSymbolAddress((void**)&p_t, g_t);
    cudaGetSymbolAddress((void**)&p_a3, g_a3);
    cudaGetSymbolAddress((void**)&p_b3, g_b3);
    cudaGetSymbolAddress((void**)&p_cntd, g_cntd);
    cudaGetSymbolAddress((void**)&p_cnts, g_cnts);

    dim3 blk(256);
    int g_nodeW = (NN * 32 + 255) / 256;     // warp-per-node grids
    int g_esl   = (ESL + 255) / 256;

    // ---- CSR build (dst for attention, src for bilinear) ----
    cudaMemsetAsync(p_cntd, 0, NN * sizeof(int));
    cudaMemsetAsync(p_cnts, 0, NN * sizeof(int));
    k_hist<<<g_esl, blk>>>(ei);
    k_scan2<<<2, 1024>>>();
    k_scatter<<<g_esl, blk>>>(ei);

    // ---- layer 1: xp = x @ W1^T ----
    k_split3<<<(NN * INCH + 255) / 256, blk>>>(x, p_a3, NN, INCH);
    k_wsplit3<<<(HH * INCH + 255) / 256, blk>>>(W1, p_b3, HH, INCH);
    {
        dim3 grid((HH + 127) / 128, (NN + 127) / 128);
        gemm_bf16_nt<<<grid, blk>>>(p_a3, p_b3, p_xp, NN, HH, 3 * INCH);
    }
    k_al<<<g_nodeW, blk>>>(as1, ad1);
    k_gat<<<g_nodeW, blk>>>(b1, p_h1, p_a3);   // h1 fp32 + split a3

    // ---- layer 2: xp = h1 @ W2^T ----
    k_wsplit3<<<(HH * HH + 255) / 256, blk>>>(W2, p_b3, HH, HH);
    {
        dim3 grid((HH + 127) / 128, (NN + 127) / 128);
        gemm_bf16_nt<<<grid, blk>>>(p_a3, p_b3, p_xp, NN, HH, 3 * HH);
    }
    k_al<<<g_nodeW, blk>>>(as2, ad2);
    k_gat<<<g_nodeW, blk>>>(b2, out_h, p_a3);  // out_h fp32 + split a3

    // ---- node predictor ----
    {
        dim3 grid((OUTN + 63) / 64, (NN + 63) / 64);
        sgemm_nt<<<grid, blk>>>(out_h, Wn, out_node, bn, NN, OUTN, HH);
    }

    // ---- edge bilinear: t = h @ WbT (a3 already holds split of out_h) ----
    k_wbt_split3<<<(OUTE * HH * HH + 255) / 256, blk>>>(Wb);
    {
        dim3 grid((OUTE * HH) / 128, (NN + 127) / 128);
        gemm_bf16_nt<<<grid, blk>>>(p_a3, p_b3, p_t, NN, OUTE * HH, 3 * HH);
    }
    k_bil<<<g_nodeW, blk>>>(out_h, bb, out_edge);
}

// round 8
// speedup vs baseline: 3.2713x; 1.0687x over previous
#include <cuda_runtime.h>
#include <cuda_bf16.h>
#include <math.h>

#define NN   50000
#define EE   800000
#define ESL  (EE + NN)
#define INCH 128
#define HID  64
#define NH   4
#define HH   256
#define OUTN 16
#define OUTE 4

// ---------------- scratch (__device__ globals: allocation-free rule) ----------------
__device__ float         g_xp[(size_t)NN * HH];
__device__ float         g_h1[(size_t)NN * HH];
__device__ float         g_als[NN * NH];
__device__ float         g_ald[NN * NH];
__device__ float         g_t[(size_t)NN * OUTE * HH];           // [N, 1024]
__device__ __nv_bfloat16 g_a3[(size_t)NN * (3 * HH)];           // 3-way split activations
__device__ __nv_bfloat16 g_b3a[(size_t)HH * (3 * INCH)];        // split W1
__device__ __nv_bfloat16 g_b3b[(size_t)HH * (3 * HH)];          // split W2
__device__ __nv_bfloat16 g_b3c[(size_t)(OUTE * HH) * (3 * HH)]; // split WbT
// CSR scratch
__device__ int g_cntd[NN], g_offd[NN + 1], g_curd[NN], g_srcd[ESL];
__device__ int g_cnts[NN], g_offs[NN + 1], g_curs[NN], g_dsts[EE], g_oids[EE];

// ---------------- helpers ----------------
__device__ __forceinline__ void ldsm_x4(unsigned &r0, unsigned &r1, unsigned &r2, unsigned &r3, unsigned addr) {
    asm volatile("ldmatrix.sync.aligned.m8n8.x4.shared.b16 {%0,%1,%2,%3}, [%4];"
                 : "=r"(r0), "=r"(r1), "=r"(r2), "=r"(r3) : "r"(addr));
}
__device__ __forceinline__ void mma_bf16(float &c0, float &c1, float &c2, float &c3,
                                         unsigned a0, unsigned a1, unsigned a2, unsigned a3,
                                         unsigned b0, unsigned b1) {
    asm volatile("mma.sync.aligned.m16n8k16.row.col.f32.bf16.bf16.f32 "
                 "{%0,%1,%2,%3}, {%4,%5,%6,%7}, {%8,%9}, {%0,%1,%2,%3};"
                 : "+f"(c0), "+f"(c1), "+f"(c2), "+f"(c3)
                 : "r"(a0), "r"(a1), "r"(a2), "r"(a3), "r"(b0), "r"(b1));
}
__device__ __forceinline__ void cp16(unsigned dst, const void* src) {
    asm volatile("cp.async.cg.shared.global [%0], [%1], 16;" :: "r"(dst), "l"(src));
}
__device__ __forceinline__ unsigned pack_bf16(float a, float b) {
    __nv_bfloat162 t = __floats2bfloat162_rn(a, b);
    return *(unsigned*)&t;
}

// ---------------- CSR build ----------------
__global__ void k_hist(const int* __restrict__ ei) {
    int idx = blockIdx.x * blockDim.x + threadIdx.x;
    if (idx >= ESL) return;
    int d = (idx < EE) ? ei[EE + idx] : (idx - EE);
    atomicAdd(&g_cntd[d], 1);
    if (idx < EE) atomicAdd(&g_cnts[ei[idx]], 1);
}

__global__ void k_scan2() {
    int* cnt = blockIdx.x ? g_cnts : g_cntd;
    int* off = blockIdx.x ? g_offs : g_offd;
    int* cur = blockIdx.x ? g_curs : g_curd;
    __shared__ int part[1024];
    int tid = threadIdx.x;
    const int per = (NN + 1023) / 1024;
    int lo = tid * per, hi = min(lo + per, NN);
    int s = 0;
    for (int i = lo; i < hi; i++) s += cnt[i];
    part[tid] = s;
    __syncthreads();
    for (int d = 1; d < 1024; d <<= 1) {
        int v = (tid >= d) ? part[tid - d] : 0;
        __syncthreads();
        part[tid] += v;
        __syncthreads();
    }
    int run = tid ? part[tid - 1] : 0;
    for (int i = lo; i < hi; i++) { off[i] = run; cur[i] = run; run += cnt[i]; }
    if (tid == 1023) off[NN] = part[1023];
}

__global__ void k_scatter(const int* __restrict__ ei) {
    int idx = blockIdx.x * blockDim.x + threadIdx.x;
    if (idx >= ESL) return;
    int s = (idx < EE) ? ei[idx] : (idx - EE);
    int d = (idx < EE) ? ei[EE + idx] : (idx - EE);
    int pos = atomicAdd(&g_curd[d], 1);
    g_srcd[pos] = s;
    if (idx < EE) {
        int p2 = atomicAdd(&g_curs[s], 1);
        g_dsts[p2] = d;
        g_oids[p2] = idx;
    }
}

// ---------------- 3-way split fp32 -> bf16, out layout [R, 3K] = [hi | lo | hi] ----------------
__global__ void k_split3(const float* __restrict__ in, __nv_bfloat16* __restrict__ out, int R, int K) {
    int idx = blockIdx.x * blockDim.x + threadIdx.x;
    if (idx >= R * K) return;
    int r = idx / K, k = idx - r * K;
    float v = in[idx];
    __nv_bfloat16 hi = __float2bfloat16(v);
    float lo = v - __bfloat162float(hi);
    size_t base = (size_t)r * (3 * K);
    out[base + k] = hi;
    out[base + K + k] = __float2bfloat16(lo);
    out[base + 2 * K + k] = hi;
}

// fp32 weights W[R,K] -> split rows [b_hi | b_hi | b_lo]
__global__ void k_wsplit3(const float* __restrict__ W, __nv_bfloat16* __restrict__ out, int R, int K) {
    int idx = blockIdx.x * blockDim.x + threadIdx.x;
    if (idx >= R * K) return;
    int r = idx / K, k = idx - r * K;
    float v = W[idx];
    __nv_bfloat16 hi = __float2bfloat16(v);
    float lo = v - __bfloat162float(hi);
    size_t base = (size_t)r * (3 * K);
    out[base + k] = hi;
    out[base + K + k] = hi;
    out[base + 2 * K + k] = __float2bfloat16(lo);
}

// Wb[o,i,j] -> split-transposed row (o*HH+j): [hi(i) | hi(i) | lo(i)]
__global__ void k_wbt_split3(const float* __restrict__ Wb) {
    int idx = blockIdx.x * blockDim.x + threadIdx.x;
    if (idx >= OUTE * HH * HH) return;
    int o = idx / (HH * HH);
    int i = (idx / HH) % HH;
    int j = idx % HH;
    float v = Wb[idx];
    __nv_bfloat16 hi = __float2bfloat16(v);
    float lo = v - __bfloat162float(hi);
    size_t base = ((size_t)o * HH + j) * (3 * HH);
    g_b3c[base + i] = hi;
    g_b3c[base + HH + i] = hi;
    g_b3c[base + 2 * HH + i] = __float2bfloat16(lo);
}

// ---------------- bf16 tensor-core GEMM: C[M,Nc] = A[M,K2] * B[Nc,K2]^T ----------------
// 128x128 block tile, BK=32, 4-stage cp.async pipeline, 8 warps (2x4) of 64x32.
#define SWZ(row, c) (((row) * 4 + ((c) ^ (((row) >> 1) & 3))) * 16)
__global__ void __launch_bounds__(256) gemm_bf16_nt(const __nv_bfloat16* __restrict__ A,
                                                    const __nv_bfloat16* __restrict__ B,
                                                    float* __restrict__ C,
                                                    int M, int Nc, int K2) {
    __shared__ __nv_bfloat16 As[4][128 * 32];
    __shared__ __nv_bfloat16 Bs[4][128 * 32];
    const int tid = threadIdx.x;
    const int wid = tid >> 5, lane = tid & 31;
    const int bm = blockIdx.y * 128, bn = blockIdx.x * 128;
    const int wm = (wid >> 2) * 64, wn = (wid & 3) * 32;

    const unsigned as_base = (unsigned)__cvta_generic_to_shared(&As[0][0]);
    const unsigned bs_base = (unsigned)__cvta_generic_to_shared(&Bs[0][0]);

    float acc[4][4][4];
#pragma unroll
    for (int i = 0; i < 4; i++)
#pragma unroll
        for (int j = 0; j < 4; j++)
#pragma unroll
            for (int k = 0; k < 4; k++) acc[i][j][k] = 0.f;

    const int KT = K2 >> 5;
    const int lrow0 = tid >> 2, lrow1 = (tid >> 2) + 64, lc = tid & 3;

    auto load_stage = [&](int kt, int s) {
        const int k0 = kt * 32;
        const unsigned as_s = as_base + s * 8192;
        const unsigned bs_s = bs_base + s * 8192;
        {
            int gr = bm + lrow0;
            if (gr < M) cp16(as_s + SWZ(lrow0, lc), A + (size_t)gr * K2 + k0 + lc * 8);
            else { uint4 z = {0,0,0,0}; *(uint4*)&As[s][(size_t)(SWZ(lrow0, lc) >> 1)] = z; }
        }
        {
            int gr = bm + lrow1;
            if (gr < M) cp16(as_s + SWZ(lrow1, lc), A + (size_t)gr * K2 + k0 + lc * 8);
            else { uint4 z = {0,0,0,0}; *(uint4*)&As[s][(size_t)(SWZ(lrow1, lc) >> 1)] = z; }
        }
        {
            int gn = bn + lrow0;
            if (gn < Nc) cp16(bs_s + SWZ(lrow0, lc), B + (size_t)gn * K2 + k0 + lc * 8);
            else { uint4 z = {0,0,0,0}; *(uint4*)&Bs[s][(size_t)(SWZ(lrow0, lc) >> 1)] = z; }
        }
        {
            int gn = bn + lrow1;
            if (gn < Nc) cp16(bs_s + SWZ(lrow1, lc), B + (size_t)gn * K2 + k0 + lc * 8);
            else { uint4 z = {0,0,0,0}; *(uint4*)&Bs[s][(size_t)(SWZ(lrow1, lc) >> 1)] = z; }
        }
        asm volatile("cp.async.commit_group;");
    };

    load_stage(0, 0);
    load_stage(1, 1);
    load_stage(2, 2);
    for (int kt = 0; kt < KT; kt++) {
        const int s = kt & 3;
        asm volatile("cp.async.wait_group 2;");
        __syncthreads();
        if (kt + 3 < KT) load_stage(kt + 3, (kt + 3) & 3);

        const unsigned as_s = as_base + s * 8192;
        const unsigned bs_s = bs_base + s * 8192;
#pragma unroll
        for (int ks = 0; ks < 2; ks++) {
            unsigned a[4][4], b[2][4];
            const int kc = ks * 2 + (lane >> 4);
#pragma unroll
            for (int mf = 0; mf < 4; mf++) {
                int row = wm + mf * 16 + (lane & 15);
                ldsm_x4(a[mf][0], a[mf][1], a[mf][2], a[mf][3], as_s + SWZ(row, kc));
            }
#pragma unroll
            for (int nf2 = 0; nf2 < 2; nf2++) {
                int row = wn + nf2 * 16 + (lane & 15);
                ldsm_x4(b[nf2][0], b[nf2][1], b[nf2][2], b[nf2][3], bs_s + SWZ(row, kc));
            }
#pragma unroll
            for (int mf = 0; mf < 4; mf++)
#pragma unroll
                for (int nf = 0; nf < 4; nf++) {
                    int nf2 = nf >> 1, w = nf & 1;
                    mma_bf16(acc[mf][nf][0], acc[mf][nf][1], acc[mf][nf][2], acc[mf][nf][3],
                             a[mf][0], a[mf][1], a[mf][2], a[mf][3],
                             b[nf2][w], b[nf2][w + 2]);
                }
        }
        __syncthreads();
    }

#pragma unroll
    for (int mf = 0; mf < 4; mf++)
#pragma unroll
        for (int nf = 0; nf < 4; nf++) {
            int r0 = bm + wm + mf * 16 + (lane >> 2);
            int c0 = bn + wn + nf * 8 + (lane & 3) * 2;
            if (c0 < Nc) {
                if (r0 < M) {
                    float2 v = {acc[mf][nf][0], acc[mf][nf][1]};
                    *(float2*)&C[(size_t)r0 * Nc + c0] = v;
                }
                if (r0 + 8 < M) {
                    float2 v = {acc[mf][nf][2], acc[mf][nf][3]};
                    *(float2*)&C[(size_t)(r0 + 8) * Nc + c0] = v;
                }
            }
        }
}
#undef SWZ

// ---------------- attention logits: warp per node, coalesced ----------------
__global__ void k_al(const float* __restrict__ a_s, const float* __restrict__ a_d) {
    int n = (blockIdx.x * blockDim.x + threadIdx.x) >> 5;
    int lane = threadIdx.x & 31;
    if (n >= NN) return;
    int hb = lane >> 3, w = lane & 7;
    const float4* xr = (const float4*)(g_xp + (size_t)n * HH);
    float4 v0 = xr[hb * 16 + w * 2];
    float4 v1 = xr[hb * 16 + w * 2 + 1];
    const float4* as4 = (const float4*)a_s;
    const float4* ad4 = (const float4*)a_d;
    float4 s0 = __ldg(&as4[hb * 16 + w * 2]), s1 = __ldg(&as4[hb * 16 + w * 2 + 1]);
    float4 d0 = __ldg(&ad4[hb * 16 + w * 2]), d1 = __ldg(&ad4[hb * 16 + w * 2 + 1]);
    float ps = v0.x * s0.x + v0.y * s0.y + v0.z * s0.z + v0.w * s0.w
             + v1.x * s1.x + v1.y * s1.y + v1.z * s1.z + v1.w * s1.w;
    float pd = v0.x * d0.x + v0.y * d0.y + v0.z * d0.z + v0.w * d0.w
             + v1.x * d1.x + v1.y * d1.y + v1.z * d1.z + v1.w * d1.w;
#pragma unroll
    for (int off = 1; off < 8; off <<= 1) {
        ps += __shfl_xor_sync(0xffffffffu, ps, off);
        pd += __shfl_xor_sync(0xffffffffu, pd, off);
    }
    if (w == 0) {
        g_als[n * NH + hb] = ps;
        g_ald[n * NH + hb] = pd;
    }
}

// ---------------- fused GAT aggregation: warp per dst node ----------------
__global__ void k_gat(const float* __restrict__ bias, float* __restrict__ outh,
                      __nv_bfloat16* __restrict__ a3out) {
    int n = (blockIdx.x * blockDim.x + threadIdx.x) >> 5;
    int lane = threadIdx.x & 31;
    if (n >= NN) return;
    int start = g_offd[n], end = g_offd[n + 1];

    // phase A: lane handles edges start+q (stride 8) for head h; online softmax
    int h = lane & 3, q = lane >> 2;
    float ald_h = g_ald[n * NH + h];
    float m = -1e30f, den = 0.f;
    for (int j = start + q; j < end; j += 8) {
        int s = g_srcd[j];
        float a = g_als[s * NH + h] + ald_h;
        a = (a > 0.f) ? a : 0.2f * a;
        if (a > m) { den = den * expf(m - a) + 1.f; m = a; }
        else den += expf(a - m);
    }
#pragma unroll
    for (int off = 4; off < 32; off <<= 1) {
        float mo = __shfl_xor_sync(0xffffffffu, m, off);
        float dn = __shfl_xor_sync(0xffffffffu, den, off);
        float mn = fmaxf(m, mo);
        den = den * expf(m - mn) + dn * expf(mo - mn);
        m = mn;
    }
    __syncwarp();

    // phase B: lane covers channels [lane*8, lane*8+8), head hb = lane>>3
    int hb = lane >> 3;
    float mB = __shfl_sync(0xffffffffu, m, hb);
    float dB = __shfl_sync(0xffffffffu, den, hb);
    float ald_hb = g_ald[n * NH + hb];
    float inv = 1.f / (dB + 1e-16f);
    float4 a0 = {0, 0, 0, 0}, a1 = {0, 0, 0, 0};
    for (int j = start; j < end; j++) {
        int s = g_srcd[j];
        float al = g_als[s * NH + hb] + ald_hb;
        al = (al > 0.f) ? al : 0.2f * al;
        float coef = expf(al - mB) * inv;
        const float4* xr = (const float4*)(g_xp + (size_t)s * HH);
        float4 v0 = xr[lane * 2], v1 = xr[lane * 2 + 1];
        a0.x += v0.x * coef; a0.y += v0.y * coef; a0.z += v0.z * coef; a0.w += v0.w * coef;
        a1.x += v1.x * coef; a1.y += v1.y * coef; a1.z += v1.z * coef; a1.w += v1.w * coef;
    }

    // epilogue: bias + ELU
    const float4* b4 = (const float4*)bias;
    float4 bb0 = __ldg(&b4[lane * 2]), bb1 = __ldg(&b4[lane * 2 + 1]);
    float v[8];
    v[0] = a0.x + bb0.x; v[1] = a0.y + bb0.y; v[2] = a0.z + bb0.z; v[3] = a0.w + bb0.w;
    v[4] = a1.x + bb1.x; v[5] = a1.y + bb1.y; v[6] = a1.z + bb1.z; v[7] = a1.w + bb1.w;
#pragma unroll
    for (int i = 0; i < 8; i++) v[i] = (v[i] > 0.f) ? v[i] : expm1f(v[i]);

    float4* orow = (float4*)(outh + (size_t)n * HH);
    float4 o0 = {v[0], v[1], v[2], v[3]}, o1 = {v[4], v[5], v[6], v[7]};
    orow[lane * 2] = o0;
    orow[lane * 2 + 1] = o1;

    // bf16 3-way split: [hi(256) | lo(256) | hi(256)]
    unsigned hi_p[4], lo_p[4];
    float hif[8];
#pragma unroll
    for (int i = 0; i < 8; i++) {
        __nv_bfloat16 hb16 = __float2bfloat16(v[i]);
        hif[i] = __bfloat162float(hb16);
    }
#pragma unroll
    for (int i = 0; i < 4; i++) {
        hi_p[i] = pack_bf16(hif[2 * i], hif[2 * i + 1]);
        lo_p[i] = pack_bf16(v[2 * i] - hif[2 * i], v[2 * i + 1] - hif[2 * i + 1]);
    }
    __nv_bfloat16* arow = a3out + (size_t)n * (3 * HH);
    uint4 hv = {hi_p[0], hi_p[1], hi_p[2], hi_p[3]};
    uint4 lv = {lo_p[0], lo_p[1], lo_p[2], lo_p[3]};
    ((uint4*)(arow))[lane] = hv;
    ((uint4*)(arow + HH))[lane] = lv;
    ((uint4*)(arow + 2 * HH))[lane] = hv;
}

// ---------------- node predictor: warp per node, Wn in smem ----------------
__global__ void __launch_bounds__(256) k_nodepred(const float* __restrict__ h,
                                                  const float* __restrict__ Wn,
                                                  const float* __restrict__ bn,
                                                  float* __restrict__ out) {
    __shared__ float sW[OUTN * HH];
    int tid = threadIdx.x;
    for (int i = tid; i < OUTN * HH; i += 256) sW[i] = Wn[i];
    __syncthreads();
    int n = (blockIdx.x * 256 + tid) >> 5;
    int lane = tid & 31;
    if (n >= NN) return;
    const float4* hr = (const float4*)(h + (size_t)n * HH);
    float4 v0 = hr[lane * 2], v1 = hr[lane * 2 + 1];
    float p[OUTN];
#pragma unroll
    for (int o = 0; o < OUTN; o++) {
        const float4* wr = (const float4*)(sW + o * HH);
        float4 w0 = wr[lane * 2], w1 = wr[lane * 2 + 1];
        p[o] = v0.x * w0.x + v0.y * w0.y + v0.z * w0.z + v0.w * w0.w
             + v1.x * w1.x + v1.y * w1.y + v1.z * w1.z + v1.w * w1.w;
    }
#pragma unroll
    for (int off = 16; off > 0; off >>= 1)
#pragma unroll
        for (int o = 0; o < OUTN; o++)
            p[o] += __shfl_xor_sync(0xffffffffu, p[o], off);
    if (lane < OUTN) out[(size_t)n * OUTN + lane] = p[lane] + __ldg(&bn[lane]);
}

// ---------------- edge bilinear: warp per src node (src-CSR), t in registers ----------------
__global__ void k_bil(const float* __restrict__ h2, const float* __restrict__ bb,
                      float* __restrict__ out_edge) {
    int n = (blockIdx.x * blockDim.x + threadIdx.x) >> 5;
    int lane = threadIdx.x & 31;
    if (n >= NN) return;
    int start = g_offs[n], end = g_offs[n + 1];
    if (start == end) return;

    const float4* tp = (const float4*)(g_t + (size_t)n * (OUTE * HH));
    float4 t0[OUTE], t1[OUTE];
#pragma unroll
    for (int o = 0; o < OUTE; o++) {
        t0[o] = tp[o * 64 + lane * 2];
        t1[o] = tp[o * 64 + lane * 2 + 1];
    }
    float myb = (lane < OUTE) ? __ldg(&bb[lane]) : 0.f;

    for (int j = start; j < end; j++) {
        int d = g_dsts[j];
        int orig = g_oids[j];
        const float4* hr = (const float4*)(h2 + (size_t)d * HH);
        float4 v0 = hr[lane * 2], v1 = hr[lane * 2 + 1];
        float p[OUTE];
#pragma unroll
        for (int o = 0; o < OUTE; o++)
            p[o] = t0[o].x * v0.x + t0[o].y * v0.y + t0[o].z * v0.z + t0[o].w * v0.w
                 + t1[o].x * v1.x + t1[o].y * v1.y + t1[o].z * v1.z + t1[o].w * v1.w;
#pragma unroll
        for (int off = 16; off > 0; off >>= 1)
#pragma unroll
            for (int o = 0; o < OUTE; o++)
                p[o] += __shfl_xor_sync(0xffffffffu, p[o], off);
        if (lane < OUTE) {
            float r = (lane == 0) ? p[0] : (lane == 1) ? p[1] : (lane == 2) ? p[2] : p[3];
            out_edge[(size_t)orig * OUTE + lane] = r + myb;
        }
    }
}

// ---------------- host ----------------
extern "C" void kernel_launch(void* const* d_in, const int* in_sizes, int n_in,
                              void* d_out, int out_size) {
    const float* x   = (const float*)d_in[0];
    const int*   ei  = (const int*)d_in[1];
    const float* W1  = (const float*)d_in[2];
    const float* as1 = (const float*)d_in[3];
    const float* ad1 = (const float*)d_in[4];
    const float* b1  = (const float*)d_in[5];
    const float* W2  = (const float*)d_in[6];
    const float* as2 = (const float*)d_in[7];
    const float* ad2 = (const float*)d_in[8];
    const float* b2  = (const float*)d_in[9];
    const float* Wn  = (const float*)d_in[10];
    const float* bn  = (const float*)d_in[11];
    const float* Wb  = (const float*)d_in[12];
    const float* bb  = (const float*)d_in[13];

    float* out_node = (float*)d_out;
    float* out_edge = out_node + (size_t)NN * OUTN;
    float* out_h    = out_edge + (size_t)EE * OUTE;

    float *p_xp, *p_h1, *p_t;
    __nv_bfloat16 *p_a3, *p_b3a, *p_b3b, *p_b3c;
    int *p_cntd, *p_cnts;
    cudaGetSymbolAddress((void**)&p_xp, g_xp);
    cudaGetSymbolAddress((void**)&p_h1, g_h1);
    cudaGetSymbolAddress((void**)&p_t, g_t);
    cudaGetSymbolAddress((void**)&p_a3, g_a3);
    cudaGetSymbolAddress((void**)&p_b3a, g_b3a);
    cudaGetSymbolAddress((void**)&p_b3b, g_b3b);
    cudaGetSymbolAddress((void**)&p_b3c, g_b3c);
    cudaGetSymbolAddress((void**)&p_cntd, g_cntd);
    cudaGetSymbolAddress((void**)&p_cnts, g_cnts);

    // one-time host resources (no device memory involved beyond driver internals)
    static cudaStream_t s2 = nullptr;
    static cudaEvent_t e0 = nullptr, e2 = nullptr, e3 = nullptr, e4 = nullptr;
    if (!s2) {
        cudaStreamCreateWithFlags(&s2, cudaStreamNonBlocking);
        cudaEventCreateWithFlags(&e0, cudaEventDisableTiming);
        cudaEventCreateWithFlags(&e2, cudaEventDisableTiming);
        cudaEventCreateWithFlags(&e3, cudaEventDisableTiming);
        cudaEventCreateWithFlags(&e4, cudaEventDisableTiming);
    }

    dim3 blk(256);
    int g_nodeW = (NN * 32 + 255) / 256;     // warp-per-node grids
    int g_esl   = (ESL + 255) / 256;

    // ---- fork: CSR build + W2/Wb splits on s2, concurrent with layer-1 GEMM path ----
    cudaEventRecord(e0, 0);
    cudaStreamWaitEvent(s2, e0, 0);
    cudaMemsetAsync(p_cntd, 0, NN * sizeof(int), s2);
    cudaMemsetAsync(p_cnts, 0, NN * sizeof(int), s2);
    k_hist<<<g_esl, blk, 0, s2>>>(ei);
    k_scan2<<<2, 1024, 0, s2>>>();
    k_scatter<<<g_esl, blk, 0, s2>>>(ei);
    k_wsplit3<<<(HH * HH + 255) / 256, blk, 0, s2>>>(W2, p_b3b, HH, HH);
    k_wbt_split3<<<(OUTE * HH * HH + 255) / 256, blk, 0, s2>>>(Wb);
    cudaEventRecord(e2, s2);

    // ---- main stream: layer 1 GEMM path ----
    k_split3<<<(NN * INCH + 255) / 256, blk>>>(x, p_a3, NN, INCH);
    k_wsplit3<<<(HH * INCH + 255) / 256, blk>>>(W1, p_b3a, HH, INCH);
    {
        dim3 grid((HH + 127) / 128, (NN + 127) / 128);
        gemm_bf16_nt<<<grid, blk>>>(p_a3, p_b3a, p_xp, NN, HH, 3 * INCH);
    }
    k_al<<<g_nodeW, blk>>>(as1, ad1);
    cudaStreamWaitEvent(0, e2, 0);             // join: need CSR before k_gat
    k_gat<<<g_nodeW, blk>>>(b1, p_h1, p_a3);   // h1 fp32 + split a3

    // ---- layer 2 ----
    {
        dim3 grid((HH + 127) / 128, (NN + 127) / 128);
        gemm_bf16_nt<<<grid, blk>>>(p_a3, p_b3b, p_xp, NN, HH, 3 * HH);
    }
    k_al<<<g_nodeW, blk>>>(as2, ad2);
    k_gat<<<g_nodeW, blk>>>(b2, out_h, p_a3);  // out_h fp32 + split a3

    // ---- fork: node predictor on s2, concurrent with t-GEMM ----
    cudaEventRecord(e3, 0);
    cudaStreamWaitEvent(s2, e3, 0);
    k_nodepred<<<(NN * 32 + 255) / 256, blk, 0, s2>>>(out_h, Wn, bn, out_node);
    cudaEventRecord(e4, s2);

    // ---- t = h @ WbT, then per-edge bilinear dot ----
    {
        dim3 grid((OUTE * HH) / 128, (NN + 127) / 128);
        gemm_bf16_nt<<<grid, blk>>>(p_a3, p_b3c, p_t, NN, OUTE * HH, 3 * HH);
    }
    k_bil<<<g_nodeW, blk>>>(out_h, bb, out_edge);
    cudaStreamWaitEvent(0, e4, 0);             // join before return
}